// round 6
// baseline (speedup 1.0000x reference)
#include <cuda_runtime.h>
#include <cuda_fp16.h>
#include <cstdint>

// ---------------- problem constants ----------------
#define NTOK 8192
#define INF  4096
#define OUTF 4096
#define NEXP 8
#define RANK 16
// SCALING = 16/16 = 1.0

// ---------------- big GEMM config (base) ----------------
#define BM 128
#define BN 256
#define BK 32                  // fp16 per K-chunk
#define KT (INF / BK)          // 128 iterations
#define NSTAGE 4
#define XTILE_B (BM * 64)      // 8192  (128 rows x 32 fp16, 64B rows)
#define WTILE_B (BN * 64)      // 16384 (256 rows x 32 fp16)
#define STAGE_B (XTILE_B + WTILE_B)       // 24576
#define SMEM_BIG (NSTAGE * STAGE_B)       // 98304

// ---------------- small GEMM config (loraA) ----------------
#define SBM 128
#define SBN 128
#define STILE_B 8192
#define SSTAGE_B (2 * STILE_B)
#define SMEM_SMALL (4 * SSTAGE_B)         // 64 KB

// ---------------- scratch (device globals) ----------------
__device__ __half g_Xh[(size_t)NTOK * INF];
__device__ __half g_Wh[(size_t)OUTF * INF];
__device__ __half g_Ah[(size_t)NEXP * RANK * INF];     // all-expert A, fp16
__device__ float  g_inter[(size_t)NTOK * NEXP * RANK]; // x @ A_all^T
__device__ int    g_idx [NTOK * 2];
__device__ float  g_wts [NTOK * 2];
__device__ float  g_coef[NTOK * 2 * RANK];

// ---------------- helpers ----------------
__device__ __forceinline__ uint32_t smem_u32(const void* p) {
    uint32_t a;
    asm("{ .reg .u64 t; cvta.to.shared.u64 t, %1; cvt.u32.u64 %0, t; }" : "=r"(a) : "l"(p));
    return a;
}
// 16B-chunk XOR swizzle inside an Nx32 fp16 tile (64B packed rows)
__device__ __forceinline__ uint32_t swz(uint32_t row, uint32_t kc) {
    return row * 64u + (((kc ^ (row >> 1)) & 3u) << 4);
}
__device__ __forceinline__ void ldsm_x4(uint32_t (&r)[4], uint32_t addr) {
    asm volatile("ldmatrix.sync.aligned.m8n8.x4.shared.b16 {%0,%1,%2,%3}, [%4];"
        : "=r"(r[0]), "=r"(r[1]), "=r"(r[2]), "=r"(r[3]) : "r"(addr));
}
__device__ __forceinline__ void mma_fp16(float (&c)[4], const uint32_t (&a)[4],
                                         uint32_t b0, uint32_t b1) {
    asm volatile("mma.sync.aligned.m16n8k16.row.col.f32.f16.f16.f32 "
        "{%0,%1,%2,%3}, {%4,%5,%6,%7}, {%8,%9}, {%0,%1,%2,%3};"
        : "+f"(c[0]), "+f"(c[1]), "+f"(c[2]), "+f"(c[3])
        : "r"(a[0]), "r"(a[1]), "r"(a[2]), "r"(a[3]), "r"(b0), "r"(b1));
}
__device__ __forceinline__ void cp16(uint32_t saddr, const void* gaddr) {
    asm volatile("cp.async.cg.shared.global [%0], [%1], 16;" :: "r"(saddr), "l"(gaddr));
}

// ---------------- 0. fp32 -> fp16 ----------------
__global__ void __launch_bounds__(256) convert1_kernel(
    const float* __restrict__ src, __half* __restrict__ hi, int n4)
{
    int i = blockIdx.x * 256 + threadIdx.x;
    if (i >= n4) return;
    float4 v = ((const float4*)src)[i];
    __half2 H01{__float2half(v.x), __float2half(v.y)};
    __half2 H23{__float2half(v.z), __float2half(v.w)};
    uint2 H{*(uint32_t*)&H01, *(uint32_t*)&H23};
    ((uint2*)hi)[i] = H;
}

// ---------------- 1. fused router + x->fp16 convert ----------------
__global__ void __launch_bounds__(256) router_convert_kernel(
    const float* __restrict__ x, const float* __restrict__ Wr,
    __half* __restrict__ xh)
{
    const int t = blockIdx.x;
    const float4* xt = (const float4*)(x + (size_t)t * INF);
    uint2* xo = (uint2*)(xh + (size_t)t * INF);
    const float4* wr = (const float4*)Wr;

    float acc[NEXP];
#pragma unroll
    for (int e = 0; e < NEXP; e++) acc[e] = 0.f;
#pragma unroll 2
    for (int i = threadIdx.x; i < INF / 4; i += 256) {
        float4 xv = xt[i];
        __half2 H01{__float2half(xv.x), __float2half(xv.y)};
        __half2 H23{__float2half(xv.z), __float2half(xv.w)};
        uint2 H{*(uint32_t*)&H01, *(uint32_t*)&H23};
        xo[i] = H;
#pragma unroll
        for (int e = 0; e < NEXP; e++) {
            float4 wv = wr[e * (INF / 4) + i];
            acc[e] += xv.x * wv.x + xv.y * wv.y + xv.z * wv.z + xv.w * wv.w;
        }
    }
#pragma unroll
    for (int e = 0; e < NEXP; e++)
#pragma unroll
        for (int off = 16; off > 0; off >>= 1)
            acc[e] += __shfl_down_sync(0xffffffffu, acc[e], off);

    __shared__ float sred[NEXP][8];
    const int warp = threadIdx.x >> 5, lane = threadIdx.x & 31;
    if (lane == 0)
#pragma unroll
        for (int e = 0; e < NEXP; e++) sred[e][warp] = acc[e];
    __syncthreads();

    if (threadIdx.x == 0) {
        float logit[NEXP];
#pragma unroll
        for (int e = 0; e < NEXP; e++) {
            float s = 0.f;
#pragma unroll
            for (int w = 0; w < 8; w++) s += sred[e][w];
            logit[e] = s;
        }
        int i0 = 0;
#pragma unroll
        for (int e = 1; e < NEXP; e++) if (logit[e] > logit[i0]) i0 = e;
        int i1 = (i0 == 0) ? 1 : 0;
#pragma unroll
        for (int e = 0; e < NEXP; e++) {
            if (e == i0) continue;
            if (logit[e] > logit[i1]) i1 = e;
        }
        const float e1 = expf(logit[i1] - logit[i0]);
        const float inv = 1.f / (1.f + e1);
        g_idx[t * 2 + 0] = i0;  g_idx[t * 2 + 1] = i1;
        g_wts[t * 2 + 0] = inv; g_wts[t * 2 + 1] = e1 * inv;
    }
}

// ---------------- 2a. BIG fp16 GEMM: 128x256 tile, 64x64 warp tile ----------------
// out[m, n] = sum_k Xh[m,k] * Wh[n,k] + bias[n]
__global__ void __launch_bounds__(256, 1) gemm_big(
    const __half* __restrict__ Xh, const __half* __restrict__ Wh,
    const float* __restrict__ bias, float* __restrict__ out)
{
    extern __shared__ __align__(128) char smem[];
    const uint32_t sb = smem_u32(smem);
    const int tid  = threadIdx.x;
    const int wid  = tid >> 5, lane = tid & 31;
    const int wm   = wid >> 2, wn = wid & 3;          // 2 x 4 warp grid
    const int mBase = blockIdx.y * BM;
    const int nBase = blockIdx.x * BN;

    const int kc = tid & 3;
    const int r0 = tid >> 2;                          // 0..63
    const __half* pX0 = Xh + (size_t)(mBase + r0) * INF + kc * 8;
    const __half* pW0 = Wh + (size_t)(nBase + r0) * INF + kc * 8;
    const size_t RD = (size_t)64 * INF;
    const uint32_t sx0 = swz(r0, kc),        sx1 = swz(r0 + 64, kc);
    const uint32_t sw0 = swz(r0, kc),        sw1 = swz(r0 + 64, kc);
    const uint32_t sw2 = swz(r0 + 128, kc),  sw3 = swz(r0 + 192, kc);

    float acc[4][8][4];
#pragma unroll
    for (int mt = 0; mt < 4; mt++)
#pragma unroll
        for (int nt = 0; nt < 8; nt++)
#pragma unroll
            for (int q = 0; q < 4; q++) acc[mt][nt][q] = 0.f;

#define BIG_LOADS(kt, s) do {                                            \
        const uint32_t stb_ = sb + (uint32_t)(s) * STAGE_B;              \
        const int ko_ = (kt) * BK;                                       \
        cp16(stb_ + sx0, pX0 + ko_);                                     \
        cp16(stb_ + sx1, pX0 + RD + ko_);                                \
        cp16(stb_ + XTILE_B + sw0, pW0 + ko_);                           \
        cp16(stb_ + XTILE_B + sw1, pW0 + RD + ko_);                      \
        cp16(stb_ + XTILE_B + sw2, pW0 + 2 * RD + ko_);                  \
        cp16(stb_ + XTILE_B + sw3, pW0 + 3 * RD + ko_);                  \
        asm volatile("cp.async.commit_group;" ::: "memory");             \
    } while (0)

    BIG_LOADS(0, 0);
    BIG_LOADS(1, 1);
    BIG_LOADS(2, 2);

    int s = 0;
    for (int kt = 0; kt < KT; kt++) {
        if (kt + 2 < KT)      asm volatile("cp.async.wait_group 2;" ::: "memory");
        else if (kt + 1 < KT) asm volatile("cp.async.wait_group 1;" ::: "memory");
        else                  asm volatile("cp.async.wait_group 0;" ::: "memory");
        __syncthreads();

        if (kt + 3 < KT) {
            int s2 = s + 3; if (s2 >= NSTAGE) s2 -= NSTAGE;
            BIG_LOADS(kt + 3, s2);
        }

        const uint32_t stb = sb + (uint32_t)s * STAGE_B;
#pragma unroll
        for (int ks = 0; ks < 2; ks++) {
            const uint32_t kc0 = ks * 2 + (lane >> 4);
            uint32_t ah[4][4], bh[4][4];
#pragma unroll
            for (int mt = 0; mt < 4; mt++) {
                const uint32_t arow = wm * 64 + mt * 16 + (lane & 15);
                ldsm_x4(ah[mt], stb + swz(arow, kc0));
            }
#pragma unroll
            for (int nt2 = 0; nt2 < 4; nt2++) {
                const uint32_t brow = wn * 64 + nt2 * 16 + (lane & 15);
                ldsm_x4(bh[nt2], stb + XTILE_B + swz(brow, kc0));
            }
#pragma unroll
            for (int mt = 0; mt < 4; mt++)
#pragma unroll
                for (int nt2 = 0; nt2 < 4; nt2++) {
                    mma_fp16(acc[mt][2 * nt2 + 0], ah[mt], bh[nt2][0], bh[nt2][2]);
                    mma_fp16(acc[mt][2 * nt2 + 1], ah[mt], bh[nt2][1], bh[nt2][3]);
                }
        }
        s++; if (s == NSTAGE) s = 0;
    }

    // epilogue: + bias
#pragma unroll
    for (int mt = 0; mt < 4; mt++) {
        const int r = mBase + wm * 64 + mt * 16 + (lane >> 2);
#pragma unroll
        for (int nt = 0; nt < 8; nt++) {
            const int c = nBase + wn * 64 + nt * 8 + (lane & 3) * 2;
            const float2 bv = *(const float2*)(bias + c);
            float2 v0{acc[mt][nt][0] + bv.x, acc[mt][nt][1] + bv.y};
            float2 v1{acc[mt][nt][2] + bv.x, acc[mt][nt][3] + bv.y};
            *(float2*)(out + (size_t)r * OUTF + c)       = v0;
            *(float2*)(out + (size_t)(r + 8) * OUTF + c) = v1;
        }
    }
}

// ---------------- 2b. small fp16 GEMM (128x128) for loraA ----------------
__global__ void __launch_bounds__(256, 2) gemm_small(
    const __half* __restrict__ Xh, const __half* __restrict__ Wh,
    float* __restrict__ out, int ostride)
{
    extern __shared__ __align__(128) char smem[];
    const uint32_t sb = smem_u32(smem);
    const int tid  = threadIdx.x;
    const int wid  = tid >> 5, lane = tid & 31;
    const int wm   = wid >> 1, wn = wid & 1;          // 4 x 2 warp grid
    const int mBase = blockIdx.y * SBM;
    const int nBase = blockIdx.x * SBN;

    const int kc = tid & 3;
    const int r0 = tid >> 2;
    const uint32_t so_lo = swz(r0, kc);
    const uint32_t so_hi = swz(r0 + 64, kc);
    const __half* pX0 = Xh + (size_t)(mBase + r0) * INF + kc * 8;
    const __half* pW0 = Wh + (size_t)(nBase + r0) * INF + kc * 8;
    const size_t RD = (size_t)64 * INF;

    float acc[2][8][4];
#pragma unroll
    for (int mt = 0; mt < 2; mt++)
#pragma unroll
        for (int nt = 0; nt < 8; nt++)
#pragma unroll
            for (int q = 0; q < 4; q++) acc[mt][nt][q] = 0.f;

#define SMALL_LOADS(kt, s) do {                                          \
        const uint32_t stb_ = sb + (uint32_t)(s) * SSTAGE_B;             \
        const int ko_ = (kt) * BK;                                       \
        cp16(stb_ + so_lo, pX0 + ko_);                                   \
        cp16(stb_ + so_hi, pX0 + RD + ko_);                              \
        cp16(stb_ + STILE_B + so_lo, pW0 + ko_);                         \
        cp16(stb_ + STILE_B + so_hi, pW0 + RD + ko_);                    \
        asm volatile("cp.async.commit_group;" ::: "memory");             \
    } while (0)

    SMALL_LOADS(0, 0);
    SMALL_LOADS(1, 1);
    SMALL_LOADS(2, 2);

    int s = 0;
    for (int kt = 0; kt < KT; kt++) {
        if (kt + 2 < KT)      asm volatile("cp.async.wait_group 2;" ::: "memory");
        else if (kt + 1 < KT) asm volatile("cp.async.wait_group 1;" ::: "memory");
        else                  asm volatile("cp.async.wait_group 0;" ::: "memory");
        __syncthreads();

        if (kt + 3 < KT) {
            int s2 = s + 3; if (s2 >= 4) s2 -= 4;
            SMALL_LOADS(kt + 3, s2);
        }

        const uint32_t stb = sb + (uint32_t)s * SSTAGE_B;
#pragma unroll
        for (int ks = 0; ks < 2; ks++) {
            const uint32_t kc0 = ks * 2 + (lane >> 4);
            uint32_t ah[2][4];
#pragma unroll
            for (int mt = 0; mt < 2; mt++) {
                const uint32_t arow = wm * 32 + mt * 16 + (lane & 15);
                ldsm_x4(ah[mt], stb + swz(arow, kc0));
            }
#pragma unroll
            for (int nt2 = 0; nt2 < 4; nt2++) {
                const uint32_t brow = wn * 64 + nt2 * 16 + (lane & 15);
                uint32_t bh[4];
                ldsm_x4(bh, stb + STILE_B + swz(brow, kc0));
#pragma unroll
                for (int mt = 0; mt < 2; mt++) {
                    mma_fp16(acc[mt][2 * nt2 + 0], ah[mt], bh[0], bh[2]);
                    mma_fp16(acc[mt][2 * nt2 + 1], ah[mt], bh[1], bh[3]);
                }
            }
        }
        s++; if (s == 4) s = 0;
    }

#pragma unroll
    for (int mt = 0; mt < 2; mt++) {
        const int r = mBase + wm * 32 + mt * 16 + (lane >> 2);
#pragma unroll
        for (int nt = 0; nt < 8; nt++) {
            const int c = nBase + wn * 64 + nt * 8 + (lane & 3) * 2;
            float2 v0{acc[mt][nt][0], acc[mt][nt][1]};
            float2 v1{acc[mt][nt][2], acc[mt][nt][3]};
            *(float2*)(out + (size_t)r * ostride + c)       = v0;
            *(float2*)(out + (size_t)(r + 8) * ostride + c) = v1;
        }
    }
}

// ---------------- 3. gather top-k intermediate -> weighted coef ----------------
__global__ void __launch_bounds__(256) gather_kernel()
{
    const int gi = blockIdx.x * 256 + threadIdx.x;
    if (gi >= NTOK * 32) return;
    const int t  = gi >> 5;
    const int kr = gi & 31;
    const int kk = kr >> 4;
    const int r  = kr & 15;
    const int e  = g_idx[t * 2 + kk];
    g_coef[gi] = g_inter[(size_t)t * (NEXP * RANK) + e * RANK + r] * g_wts[t * 2 + kk];
}

// ---------------- 4. LoRA B apply ----------------
__global__ void __launch_bounds__(128) loraB_kernel(
    const float* __restrict__ Bw, float* __restrict__ out)
{
    const int o = blockIdx.x * 128 + threadIdx.x;
    const int tBase = blockIdx.y * 128;
    for (int tt = 0; tt < 128; tt++) {
        const int t = tBase + tt;
        const int e0 = g_idx[t * 2 + 0];
        const int e1 = g_idx[t * 2 + 1];
        const float4* b0 = (const float4*)(Bw + ((size_t)e0 * OUTF + o) * RANK);
        const float4* b1 = (const float4*)(Bw + ((size_t)e1 * OUTF + o) * RANK);
        const float4* c  = (const float4*)(g_coef + t * 32);
        float acc = 0.f;
#pragma unroll
        for (int q = 0; q < 4; q++) {
            float4 bv = b0[q]; float4 cv = c[q];
            acc += bv.x * cv.x + bv.y * cv.y + bv.z * cv.z + bv.w * cv.w;
        }
#pragma unroll
        for (int q = 0; q < 4; q++) {
            float4 bv = b1[q]; float4 cv = c[q + 4];
            acc += bv.x * cv.x + bv.y * cv.y + bv.z * cv.z + bv.w * cv.w;
        }
        out[(size_t)t * OUTF + o] += acc;
    }
}

// ---------------- launch ----------------
extern "C" void kernel_launch(void* const* d_in, const int* in_sizes, int n_in,
                              void* d_out, int out_size)
{
    const float* x   = (const float*)d_in[0];
    const float* Wb  = (const float*)d_in[1];
    const float* bb  = (const float*)d_in[2];
    const float* Wr  = (const float*)d_in[3];
    const float* Aw  = (const float*)d_in[4];
    const float* Bw  = (const float*)d_in[5];
    float* out = (float*)d_out;

    void *pXh, *pWh, *pAh, *pInter;
    cudaGetSymbolAddress(&pXh, g_Xh);
    cudaGetSymbolAddress(&pWh, g_Wh);
    cudaGetSymbolAddress(&pAh, g_Ah);
    cudaGetSymbolAddress(&pInter, g_inter);

    cudaFuncSetAttribute(gemm_big,
                         cudaFuncAttributeMaxDynamicSharedMemorySize, SMEM_BIG);
    cudaFuncSetAttribute(gemm_small,
                         cudaFuncAttributeMaxDynamicSharedMemorySize, SMEM_SMALL);

    // W / A converts
    convert1_kernel<<<(OUTF * INF / 4 + 255) / 256, 256>>>(
        Wb, (__half*)pWh, OUTF * INF / 4);
    convert1_kernel<<<(NEXP * RANK * INF / 4 + 255) / 256, 256>>>(
        Aw, (__half*)pAh, NEXP * RANK * INF / 4);

    // fused router + x convert
    router_convert_kernel<<<NTOK, 256>>>(x, Wr, (__half*)pXh);

    // LoRA A as skinny GEMM over all experts: inter = X @ A_all^T
    gemm_small<<<dim3(1, NTOK / SBM), 256, SMEM_SMALL>>>(
        (const __half*)pXh, (const __half*)pAh, (float*)pInter, NEXP * RANK);

    // gather + weight
    gather_kernel<<<(NTOK * 32 + 255) / 256, 256>>>();

    // base GEMM (128x256 tiles)
    gemm_big<<<dim3(OUTF / BN, NTOK / BM), 256, SMEM_BIG>>>(
        (const __half*)pXh, (const __half*)pWh, bb, out);

    // LoRA B
    loraB_kernel<<<dim3(OUTF / 128, NTOK / 128), 128>>>(Bw, out);
}

// round 7
// speedup vs baseline: 1.0858x; 1.0858x over previous
#include <cuda_runtime.h>
#include <cuda_fp16.h>
#include <cstdint>

// ---------------- problem constants ----------------
#define NTOK 8192
#define INF  4096
#define OUTF 4096
#define NEXP 8
#define RANK 16
// SCALING = 16/16 = 1.0

// ---------------- base GEMM config (proven round-5) ----------------
#define BM 128
#define BN 128
#define BK 32                  // fp16 per K-chunk
#define KT (INF / BK)          // 128 iterations
#define NSTAGE 4
#define TILE_B   8192          // one 128x32 fp16 tile (64B packed rows)
#define STAGE_B  (2 * TILE_B)  // Xh, Wh
#define SMEM_TOTAL (NSTAGE * STAGE_B)   // 64 KB

// ---------------- small GEMM config (loraA) ----------------
#define SBM 64
#define SBN 128
#define SXT_B (SBM * 64)       // 4096
#define SWT_B (SBN * 64)       // 8192
#define SSTAGE_B (SXT_B + SWT_B)         // 12288
#define SMEM_SMALL (4 * SSTAGE_B)        // 48 KB

// ---------------- scratch (device globals) ----------------
__device__ __half g_Xh[(size_t)NTOK * INF];
__device__ __half g_Wh[(size_t)OUTF * INF];
__device__ __half g_Ah[(size_t)NEXP * RANK * INF];     // all-expert A, fp16
__device__ float  g_inter[(size_t)NTOK * NEXP * RANK]; // x @ A_all^T
__device__ int    g_idx [NTOK * 2];
__device__ float  g_wts [NTOK * 2];
__device__ float  g_coef[NTOK * 2 * RANK];

// ---------------- helpers ----------------
__device__ __forceinline__ uint32_t smem_u32(const void* p) {
    uint32_t a;
    asm("{ .reg .u64 t; cvta.to.shared.u64 t, %1; cvt.u32.u64 %0, t; }" : "=r"(a) : "l"(p));
    return a;
}
// 16B-chunk XOR swizzle inside an Nx32 fp16 tile (64B packed rows)
__device__ __forceinline__ uint32_t swz(uint32_t row, uint32_t kc) {
    return row * 64u + (((kc ^ (row >> 1)) & 3u) << 4);
}
__device__ __forceinline__ void ldsm_x4(uint32_t (&r)[4], uint32_t addr) {
    asm volatile("ldmatrix.sync.aligned.m8n8.x4.shared.b16 {%0,%1,%2,%3}, [%4];"
        : "=r"(r[0]), "=r"(r[1]), "=r"(r[2]), "=r"(r[3]) : "r"(addr));
}
__device__ __forceinline__ void mma_fp16(float (&c)[4], const uint32_t (&a)[4],
                                         uint32_t b0, uint32_t b1) {
    asm volatile("mma.sync.aligned.m16n8k16.row.col.f32.f16.f16.f32 "
        "{%0,%1,%2,%3}, {%4,%5,%6,%7}, {%8,%9}, {%0,%1,%2,%3};"
        : "+f"(c[0]), "+f"(c[1]), "+f"(c[2]), "+f"(c[3])
        : "r"(a[0]), "r"(a[1]), "r"(a[2]), "r"(a[3]), "r"(b0), "r"(b1));
}
__device__ __forceinline__ void cp16(uint32_t saddr, const void* gaddr) {
    asm volatile("cp.async.cg.shared.global [%0], [%1], 16;" :: "r"(saddr), "l"(gaddr));
}

// ---------------- 0. fp32 -> fp16 ----------------
__global__ void __launch_bounds__(256) convert1_kernel(
    const float* __restrict__ src, __half* __restrict__ hi, int n4)
{
    int i = blockIdx.x * 256 + threadIdx.x;
    if (i >= n4) return;
    float4 v = ((const float4*)src)[i];
    __half2 H01{__float2half(v.x), __float2half(v.y)};
    __half2 H23{__float2half(v.z), __float2half(v.w)};
    uint2 H{*(uint32_t*)&H01, *(uint32_t*)&H23};
    ((uint2*)hi)[i] = H;
}

// ---------------- 1. fused router + x->fp16 convert ----------------
__global__ void __launch_bounds__(256) router_convert_kernel(
    const float* __restrict__ x, const float* __restrict__ Wr,
    __half* __restrict__ xh)
{
    const int t = blockIdx.x;
    const float4* xt = (const float4*)(x + (size_t)t * INF);
    uint2* xo = (uint2*)(xh + (size_t)t * INF);
    const float4* wr = (const float4*)Wr;

    float acc[NEXP];
#pragma unroll
    for (int e = 0; e < NEXP; e++) acc[e] = 0.f;
#pragma unroll 2
    for (int i = threadIdx.x; i < INF / 4; i += 256) {
        float4 xv = xt[i];
        __half2 H01{__float2half(xv.x), __float2half(xv.y)};
        __half2 H23{__float2half(xv.z), __float2half(xv.w)};
        uint2 H{*(uint32_t*)&H01, *(uint32_t*)&H23};
        xo[i] = H;
#pragma unroll
        for (int e = 0; e < NEXP; e++) {
            float4 wv = wr[e * (INF / 4) + i];
            acc[e] += xv.x * wv.x + xv.y * wv.y + xv.z * wv.z + xv.w * wv.w;
        }
    }
#pragma unroll
    for (int e = 0; e < NEXP; e++)
#pragma unroll
        for (int off = 16; off > 0; off >>= 1)
            acc[e] += __shfl_down_sync(0xffffffffu, acc[e], off);

    __shared__ float sred[NEXP][8];
    const int warp = threadIdx.x >> 5, lane = threadIdx.x & 31;
    if (lane == 0)
#pragma unroll
        for (int e = 0; e < NEXP; e++) sred[e][warp] = acc[e];
    __syncthreads();

    if (threadIdx.x == 0) {
        float logit[NEXP];
#pragma unroll
        for (int e = 0; e < NEXP; e++) {
            float s = 0.f;
#pragma unroll
            for (int w = 0; w < 8; w++) s += sred[e][w];
            logit[e] = s;
        }
        int i0 = 0;
#pragma unroll
        for (int e = 1; e < NEXP; e++) if (logit[e] > logit[i0]) i0 = e;
        int i1 = (i0 == 0) ? 1 : 0;
#pragma unroll
        for (int e = 0; e < NEXP; e++) {
            if (e == i0) continue;
            if (logit[e] > logit[i1]) i1 = e;
        }
        const float e1 = expf(logit[i1] - logit[i0]);
        const float inv = 1.f / (1.f + e1);
        g_idx[t * 2 + 0] = i0;  g_idx[t * 2 + 1] = i1;
        g_wts[t * 2 + 0] = inv; g_wts[t * 2 + 1] = e1 * inv;
    }
}

// ---------------- 2a. base fp16 GEMM (128x128, 2 CTA/SM) ----------------
// out[m, n] = sum_k Xh[m,k] * Wh[n,k] + bias[n]
__global__ void __launch_bounds__(256, 2) gemm_mma(
    const __half* __restrict__ Xh, const __half* __restrict__ Wh,
    const float* __restrict__ bias, float* __restrict__ out)
{
    extern __shared__ __align__(128) char smem[];
    const uint32_t sb = smem_u32(smem);
    const int tid  = threadIdx.x;
    const int wid  = tid >> 5, lane = tid & 31;
    const int wm   = wid >> 1, wn = wid & 1;          // 4 x 2 warp grid
    const int mBase = blockIdx.y * BM;
    const int nBase = blockIdx.x * BN;

    const int kc = tid & 3;
    const int r0 = tid >> 2;                          // 0..63
    const uint32_t so_lo = swz(r0, kc);
    const uint32_t so_hi = swz(r0 + 64, kc);
    const __half* pX0 = Xh + (size_t)(mBase + r0) * INF + kc * 8;
    const __half* pW0 = Wh + (size_t)(nBase + r0) * INF + kc * 8;
    const size_t RD = (size_t)64 * INF;

    float acc[2][8][4];
#pragma unroll
    for (int mt = 0; mt < 2; mt++)
#pragma unroll
        for (int nt = 0; nt < 8; nt++)
#pragma unroll
            for (int q = 0; q < 4; q++) acc[mt][nt][q] = 0.f;

#define ISSUE_LOADS(kt, s) do {                                          \
        const uint32_t stb_ = sb + (uint32_t)(s) * STAGE_B;              \
        const int ko_ = (kt) * BK;                                       \
        cp16(stb_ + so_lo, pX0 + ko_);                                   \
        cp16(stb_ + so_hi, pX0 + RD + ko_);                              \
        cp16(stb_ + TILE_B + so_lo, pW0 + ko_);                          \
        cp16(stb_ + TILE_B + so_hi, pW0 + RD + ko_);                     \
        asm volatile("cp.async.commit_group;" ::: "memory");             \
    } while (0)

    ISSUE_LOADS(0, 0);
    ISSUE_LOADS(1, 1);
    ISSUE_LOADS(2, 2);

    int s = 0;
    for (int kt = 0; kt < KT; kt++) {
        if (kt + 2 < KT)      asm volatile("cp.async.wait_group 2;" ::: "memory");
        else if (kt + 1 < KT) asm volatile("cp.async.wait_group 1;" ::: "memory");
        else                  asm volatile("cp.async.wait_group 0;" ::: "memory");
        __syncthreads();

        if (kt + 3 < KT) {
            int s2 = s + 3; if (s2 >= NSTAGE) s2 -= NSTAGE;
            ISSUE_LOADS(kt + 3, s2);
        }

        const uint32_t stb = sb + (uint32_t)s * STAGE_B;
#pragma unroll
        for (int ks = 0; ks < 2; ks++) {
            const uint32_t kc0 = ks * 2 + (lane >> 4);
            uint32_t ah[2][4];
#pragma unroll
            for (int mt = 0; mt < 2; mt++) {
                const uint32_t arow = wm * 32 + mt * 16 + (lane & 15);
                ldsm_x4(ah[mt], stb + swz(arow, kc0));
            }
#pragma unroll
            for (int nt2 = 0; nt2 < 4; nt2++) {
                const uint32_t brow = wn * 64 + nt2 * 16 + (lane & 15);
                uint32_t bh[4];
                ldsm_x4(bh, stb + TILE_B + swz(brow, kc0));
#pragma unroll
                for (int mt = 0; mt < 2; mt++) {
                    mma_fp16(acc[mt][2 * nt2 + 0], ah[mt], bh[0], bh[2]);
                    mma_fp16(acc[mt][2 * nt2 + 1], ah[mt], bh[1], bh[3]);
                }
            }
        }
        s++; if (s == NSTAGE) s = 0;
    }

    // epilogue
#pragma unroll
    for (int mt = 0; mt < 2; mt++) {
        const int r = mBase + wm * 32 + mt * 16 + (lane >> 2);
#pragma unroll
        for (int nt = 0; nt < 8; nt++) {
            const int c = nBase + wn * 64 + nt * 8 + (lane & 3) * 2;
            const float2 bv = *(const float2*)(bias + c);
            float2 v0{acc[mt][nt][0] + bv.x, acc[mt][nt][1] + bv.y};
            float2 v1{acc[mt][nt][2] + bv.x, acc[mt][nt][3] + bv.y};
            *(float2*)(out + (size_t)r * OUTF + c)       = v0;
            *(float2*)(out + (size_t)(r + 8) * OUTF + c) = v1;
        }
    }
}

// ---------------- 2b. small fp16 GEMM (64x128) for loraA ----------------
__global__ void __launch_bounds__(256, 2) gemm_small(
    const __half* __restrict__ Xh, const __half* __restrict__ Wh,
    float* __restrict__ out, int ostride)
{
    extern __shared__ __align__(128) char smem[];
    const uint32_t sb = smem_u32(smem);
    const int tid  = threadIdx.x;
    const int wid  = tid >> 5, lane = tid & 31;
    const int wm   = wid >> 1, wn = wid & 1;          // 4 x 2 warp grid, 16x64 tiles
    const int mBase = blockIdx.y * SBM;
    const int nBase = blockIdx.x * SBN;

    // loads: X tile 64 rows (1 per thread row-slot covers 64), W tile 128 rows
    const int kc = tid & 3;
    const int r0 = tid >> 2;                          // 0..63
    const uint32_t so_x  = swz(r0, kc);
    const uint32_t so_w0 = swz(r0, kc);
    const uint32_t so_w1 = swz(r0 + 64, kc);
    const __half* pX0 = Xh + (size_t)(mBase + r0) * INF + kc * 8;
    const __half* pW0 = Wh + (size_t)(nBase + r0) * INF + kc * 8;
    const size_t RD = (size_t)64 * INF;

    float acc[8][4];
#pragma unroll
    for (int nt = 0; nt < 8; nt++)
#pragma unroll
        for (int q = 0; q < 4; q++) acc[nt][q] = 0.f;

#define SMALL_LOADS(kt, s) do {                                          \
        const uint32_t stb_ = sb + (uint32_t)(s) * SSTAGE_B;             \
        const int ko_ = (kt) * BK;                                       \
        cp16(stb_ + so_x, pX0 + ko_);                                    \
        cp16(stb_ + SXT_B + so_w0, pW0 + ko_);                           \
        cp16(stb_ + SXT_B + so_w1, pW0 + RD + ko_);                      \
        asm volatile("cp.async.commit_group;" ::: "memory");             \
    } while (0)

    SMALL_LOADS(0, 0);
    SMALL_LOADS(1, 1);
    SMALL_LOADS(2, 2);

    int s = 0;
    for (int kt = 0; kt < KT; kt++) {
        if (kt + 2 < KT)      asm volatile("cp.async.wait_group 2;" ::: "memory");
        else if (kt + 1 < KT) asm volatile("cp.async.wait_group 1;" ::: "memory");
        else                  asm volatile("cp.async.wait_group 0;" ::: "memory");
        __syncthreads();

        if (kt + 3 < KT) {
            int s2 = s + 3; if (s2 >= 4) s2 -= 4;
            SMALL_LOADS(kt + 3, s2);
        }

        const uint32_t stb = sb + (uint32_t)s * SSTAGE_B;
#pragma unroll
        for (int ks = 0; ks < 2; ks++) {
            const uint32_t kc0 = ks * 2 + (lane >> 4);
            uint32_t ah[4];
            const uint32_t arow = wm * 16 + (lane & 15);
            ldsm_x4(ah, stb + swz(arow, kc0));
#pragma unroll
            for (int nt2 = 0; nt2 < 4; nt2++) {
                const uint32_t brow = wn * 64 + nt2 * 16 + (lane & 15);
                uint32_t bh[4];
                ldsm_x4(bh, stb + SXT_B + swz(brow, kc0));
                mma_fp16(acc[2 * nt2 + 0], ah, bh[0], bh[2]);
                mma_fp16(acc[2 * nt2 + 1], ah, bh[1], bh[3]);
            }
        }
        s++; if (s == 4) s = 0;
    }

    const int r = mBase + wm * 16 + (lane >> 2);
#pragma unroll
    for (int nt = 0; nt < 8; nt++) {
        const int c = nBase + wn * 64 + nt * 8 + (lane & 3) * 2;
        float2 v0{acc[nt][0], acc[nt][1]};
        float2 v1{acc[nt][2], acc[nt][3]};
        *(float2*)(out + (size_t)r * ostride + c)       = v0;
        *(float2*)(out + (size_t)(r + 8) * ostride + c) = v1;
    }
}

// ---------------- 3. gather top-k intermediate -> weighted coef ----------------
__global__ void __launch_bounds__(256) gather_kernel()
{
    const int gi = blockIdx.x * 256 + threadIdx.x;
    if (gi >= NTOK * 32) return;
    const int t  = gi >> 5;
    const int kr = gi & 31;
    const int kk = kr >> 4;
    const int r  = kr & 15;
    const int e  = g_idx[t * 2 + kk];
    g_coef[gi] = g_inter[(size_t)t * (NEXP * RANK) + e * RANK + r] * g_wts[t * 2 + kk];
}

// ---------------- 4. LoRA B apply ----------------
__global__ void __launch_bounds__(128) loraB_kernel(
    const float* __restrict__ Bw, float* __restrict__ out)
{
    const int o = blockIdx.x * 128 + threadIdx.x;
    const int tBase = blockIdx.y * 128;
    for (int tt = 0; tt < 128; tt++) {
        const int t = tBase + tt;
        const int e0 = g_idx[t * 2 + 0];
        const int e1 = g_idx[t * 2 + 1];
        const float4* b0 = (const float4*)(Bw + ((size_t)e0 * OUTF + o) * RANK);
        const float4* b1 = (const float4*)(Bw + ((size_t)e1 * OUTF + o) * RANK);
        const float4* c  = (const float4*)(g_coef + t * 32);
        float acc = 0.f;
#pragma unroll
        for (int q = 0; q < 4; q++) {
            float4 bv = b0[q]; float4 cv = c[q];
            acc += bv.x * cv.x + bv.y * cv.y + bv.z * cv.z + bv.w * cv.w;
        }
#pragma unroll
        for (int q = 0; q < 4; q++) {
            float4 bv = b1[q]; float4 cv = c[q + 4];
            acc += bv.x * cv.x + bv.y * cv.y + bv.z * cv.z + bv.w * cv.w;
        }
        out[(size_t)t * OUTF + o] += acc;
    }
}

// ---------------- launch ----------------
extern "C" void kernel_launch(void* const* d_in, const int* in_sizes, int n_in,
                              void* d_out, int out_size)
{
    const float* x   = (const float*)d_in[0];
    const float* Wb  = (const float*)d_in[1];
    const float* bb  = (const float*)d_in[2];
    const float* Wr  = (const float*)d_in[3];
    const float* Aw  = (const float*)d_in[4];
    const float* Bw  = (const float*)d_in[5];
    float* out = (float*)d_out;

    void *pXh, *pWh, *pAh, *pInter;
    cudaGetSymbolAddress(&pXh, g_Xh);
    cudaGetSymbolAddress(&pWh, g_Wh);
    cudaGetSymbolAddress(&pAh, g_Ah);
    cudaGetSymbolAddress(&pInter, g_inter);

    cudaFuncSetAttribute(gemm_mma,
                         cudaFuncAttributeMaxDynamicSharedMemorySize, SMEM_TOTAL);
    cudaFuncSetAttribute(gemm_small,
                         cudaFuncAttributeMaxDynamicSharedMemorySize, SMEM_SMALL);

    // W / A converts
    convert1_kernel<<<(OUTF * INF / 4 + 255) / 256, 256>>>(
        Wb, (__half*)pWh, OUTF * INF / 4);
    convert1_kernel<<<(NEXP * RANK * INF / 4 + 255) / 256, 256>>>(
        Aw, (__half*)pAh, NEXP * RANK * INF / 4);

    // fused router + x convert
    router_convert_kernel<<<NTOK, 256>>>(x, Wr, (__half*)pXh);

    // LoRA A as skinny GEMM over all experts: inter = X @ A_all^T
    gemm_small<<<dim3(1, NTOK / SBM), 256, SMEM_SMALL>>>(
        (const __half*)pXh, (const __half*)pAh, (float*)pInter, NEXP * RANK);

    // gather + weight
    gather_kernel<<<(NTOK * 32 + 255) / 256, 256>>>();

    // base GEMM (128x128 tiles, 2 CTA/SM)
    gemm_mma<<<dim3(OUTF / BN, NTOK / BM), 256, SMEM_TOTAL>>>(
        (const __half*)pXh, (const __half*)pWh, bb, out);

    // LoRA B
    loraB_kernel<<<dim3(OUTF / 128, NTOK / 128), 128>>>(Bw, out);
}

// round 9
// speedup vs baseline: 1.1436x; 1.0532x over previous
#include <cuda_runtime.h>
#include <cuda_fp16.h>
#include <cstdint>

// ---------------- problem constants ----------------
#define NTOK 8192
#define INF  4096
#define OUTF 4096
#define NEXP 8
#define RANK 16
// SCALING = 16/16 = 1.0

// ---------------- base GEMM config (BK=64, 3-stage) ----------------
#define BM 128
#define BN 128
#define BK2 64                   // fp16 per K-chunk (128B rows)
#define KT2 (INF / BK2)          // 64 iterations
#define NST 3
#define TILE2_B (128 * 128)      // 16384: 128 rows x 64 fp16
#define STAGE2_B (2 * TILE2_B)   // 32768
#define SMEM_BIG (NST * STAGE2_B)   // 98304

// ---------------- small GEMM config (loraA, split-K) ----------------
#define SBM 64
#define SBN 128
#define SPLITK 4
#define SKT (INF / 32 / SPLITK)  // 32 k-chunks of 32 per slice
#define SXT_B (SBM * 64)         // 4096
#define SWT_B (SBN * 64)         // 8192
#define SSTAGE_B (SXT_B + SWT_B) // 12288
#define SMEM_SMALL (4 * SSTAGE_B)   // 48 KB

// ---------------- scratch (device globals) ----------------
__device__ __half g_Xh[(size_t)NTOK * INF];
__device__ __half g_Wh[(size_t)OUTF * INF];
__device__ __half g_Ah[(size_t)NEXP * RANK * INF];        // all-expert A, fp16
__device__ float  g_interp[(size_t)SPLITK * NTOK * 128];  // split-K partials
__device__ int    g_idx [NTOK * 2];
__device__ float  g_wts [NTOK * 2];
__device__ float  g_coef[NTOK * 2 * RANK];

// ---------------- helpers ----------------
__device__ __forceinline__ uint32_t smem_u32(const void* p) {
    uint32_t a;
    asm("{ .reg .u64 t; cvta.to.shared.u64 t, %1; cvt.u32.u64 %0, t; }" : "=r"(a) : "l"(p));
    return a;
}
// 64B-row swizzle (4 chunks, 2-row period) — used by small GEMM
__device__ __forceinline__ uint32_t swz(uint32_t row, uint32_t kc) {
    return row * 64u + (((kc ^ (row >> 1)) & 3u) << 4);
}
// 128B-row swizzle (8 chunks, 8-row period) — used by base GEMM
__device__ __forceinline__ uint32_t swz2(uint32_t row, uint32_t kc) {
    return row * 128u + (((kc ^ row) & 7u) << 4);
}
__device__ __forceinline__ void ldsm_x4(uint32_t (&r)[4], uint32_t addr) {
    asm volatile("ldmatrix.sync.aligned.m8n8.x4.shared.b16 {%0,%1,%2,%3}, [%4];"
        : "=r"(r[0]), "=r"(r[1]), "=r"(r[2]), "=r"(r[3]) : "r"(addr));
}
__device__ __forceinline__ void mma_fp16(float (&c)[4], const uint32_t (&a)[4],
                                         uint32_t b0, uint32_t b1) {
    asm volatile("mma.sync.aligned.m16n8k16.row.col.f32.f16.f16.f32 "
        "{%0,%1,%2,%3}, {%4,%5,%6,%7}, {%8,%9}, {%0,%1,%2,%3};"
        : "+f"(c[0]), "+f"(c[1]), "+f"(c[2]), "+f"(c[3])
        : "r"(a[0]), "r"(a[1]), "r"(a[2]), "r"(a[3]), "r"(b0), "r"(b1));
}
__device__ __forceinline__ void cp16(uint32_t saddr, const void* gaddr) {
    asm volatile("cp.async.cg.shared.global [%0], [%1], 16;" :: "r"(saddr), "l"(gaddr));
}

// ---------------- 0. fp32 -> fp16 ----------------
__global__ void __launch_bounds__(256) convert1_kernel(
    const float* __restrict__ src, __half* __restrict__ hi, int n4)
{
    int i = blockIdx.x * 256 + threadIdx.x;
    if (i >= n4) return;
    float4 v = ((const float4*)src)[i];
    __half2 H01{__float2half(v.x), __float2half(v.y)};
    __half2 H23{__float2half(v.z), __float2half(v.w)};
    uint2 H{*(uint32_t*)&H01, *(uint32_t*)&H23};
    ((uint2*)hi)[i] = H;
}

// ---------------- 1. fused router + x->fp16 convert ----------------
__global__ void __launch_bounds__(256) router_convert_kernel(
    const float* __restrict__ x, const float* __restrict__ Wr,
    __half* __restrict__ xh)
{
    const int t = blockIdx.x;
    const float4* xt = (const float4*)(x + (size_t)t * INF);
    uint2* xo = (uint2*)(xh + (size_t)t * INF);
    const float4* wr = (const float4*)Wr;

    float acc[NEXP];
#pragma unroll
    for (int e = 0; e < NEXP; e++) acc[e] = 0.f;
#pragma unroll 2
    for (int i = threadIdx.x; i < INF / 4; i += 256) {
        float4 xv = xt[i];
        __half2 H01{__float2half(xv.x), __float2half(xv.y)};
        __half2 H23{__float2half(xv.z), __float2half(xv.w)};
        uint2 H{*(uint32_t*)&H01, *(uint32_t*)&H23};
        xo[i] = H;
#pragma unroll
        for (int e = 0; e < NEXP; e++) {
            float4 wv = wr[e * (INF / 4) + i];
            acc[e] += xv.x * wv.x + xv.y * wv.y + xv.z * wv.z + xv.w * wv.w;
        }
    }
#pragma unroll
    for (int e = 0; e < NEXP; e++)
#pragma unroll
        for (int off = 16; off > 0; off >>= 1)
            acc[e] += __shfl_down_sync(0xffffffffu, acc[e], off);

    __shared__ float sred[NEXP][8];
    const int warp = threadIdx.x >> 5, lane = threadIdx.x & 31;
    if (lane == 0)
#pragma unroll
        for (int e = 0; e < NEXP; e++) sred[e][warp] = acc[e];
    __syncthreads();

    if (threadIdx.x == 0) {
        float logit[NEXP];
#pragma unroll
        for (int e = 0; e < NEXP; e++) {
            float s = 0.f;
#pragma unroll
            for (int w = 0; w < 8; w++) s += sred[e][w];
            logit[e] = s;
        }
        int i0 = 0;
#pragma unroll
        for (int e = 1; e < NEXP; e++) if (logit[e] > logit[i0]) i0 = e;
        int i1 = (i0 == 0) ? 1 : 0;
#pragma unroll
        for (int e = 0; e < NEXP; e++) {
            if (e == i0) continue;
            if (logit[e] > logit[i1]) i1 = e;
        }
        const float e1 = expf(logit[i1] - logit[i0]);
        const float inv = 1.f / (1.f + e1);
        g_idx[t * 2 + 0] = i0;  g_idx[t * 2 + 1] = i1;
        g_wts[t * 2 + 0] = inv; g_wts[t * 2 + 1] = e1 * inv;
    }
}

// ---------------- 2a. base fp16 GEMM (128x128, BK=64, 3-stage, 2 CTA/SM) ----
// out[m, n] = sum_k Xh[m,k] * Wh[n,k] + bias[n]
__global__ void __launch_bounds__(256, 2) gemm_mma(
    const __half* __restrict__ Xh, const __half* __restrict__ Wh,
    const float* __restrict__ bias, float* __restrict__ out)
{
    extern __shared__ __align__(128) char smem[];
    const uint32_t sb = smem_u32(smem);
    const int tid  = threadIdx.x;
    const int wid  = tid >> 5, lane = tid & 31;
    const int wm   = wid >> 1, wn = wid & 1;          // 4 x 2 warp grid
    const int mBase = blockIdx.y * BM;
    const int nBase = blockIdx.x * BN;

    // load mapping: 256 threads -> 32 rows x 8 chunks per pass, 4 passes/tile
    const int lr = tid >> 3;                          // 0..31
    const int lc = tid & 7;                           // chunk 0..7
    const __half* pX0 = Xh + (size_t)(mBase + lr) * INF + lc * 8;
    const __half* pW0 = Wh + (size_t)(nBase + lr) * INF + lc * 8;
    const size_t R32 = (size_t)32 * INF;
    const uint32_t sx0 = swz2(lr,      lc);
    const uint32_t sx1 = swz2(lr + 32, lc);
    const uint32_t sx2 = swz2(lr + 64, lc);
    const uint32_t sx3 = swz2(lr + 96, lc);

    float acc[2][8][4];
#pragma unroll
    for (int mt = 0; mt < 2; mt++)
#pragma unroll
        for (int nt = 0; nt < 8; nt++)
#pragma unroll
            for (int q = 0; q < 4; q++) acc[mt][nt][q] = 0.f;

#define BIG_LOADS(kt, s) do {                                            \
        const uint32_t stb_ = sb + (uint32_t)(s) * STAGE2_B;             \
        const int ko_ = (kt) * BK2;                                      \
        cp16(stb_ + sx0, pX0 + ko_);                                     \
        cp16(stb_ + sx1, pX0 + R32 + ko_);                               \
        cp16(stb_ + sx2, pX0 + 2 * R32 + ko_);                           \
        cp16(stb_ + sx3, pX0 + 3 * R32 + ko_);                           \
        cp16(stb_ + TILE2_B + sx0, pW0 + ko_);                           \
        cp16(stb_ + TILE2_B + sx1, pW0 + R32 + ko_);                     \
        cp16(stb_ + TILE2_B + sx2, pW0 + 2 * R32 + ko_);                 \
        cp16(stb_ + TILE2_B + sx3, pW0 + 3 * R32 + ko_);                 \
        asm volatile("cp.async.commit_group;" ::: "memory");             \
    } while (0)

    BIG_LOADS(0, 0);
    BIG_LOADS(1, 1);

    int s = 0;
    for (int kt = 0; kt < KT2; kt++) {
        if (kt + 1 < KT2) asm volatile("cp.async.wait_group 1;" ::: "memory");
        else              asm volatile("cp.async.wait_group 0;" ::: "memory");
        __syncthreads();

        if (kt + 2 < KT2) {
            int s2 = s + 2; if (s2 >= NST) s2 -= NST;
            BIG_LOADS(kt + 2, s2);
        }

        const uint32_t stb = sb + (uint32_t)s * STAGE2_B;
#pragma unroll
        for (int ks = 0; ks < 4; ks++) {              // four k16 steps per BK2=64
            const uint32_t kc0 = ks * 2 + (lane >> 4);
            uint32_t ah[2][4];
#pragma unroll
            for (int mt = 0; mt < 2; mt++) {
                const uint32_t arow = wm * 32 + mt * 16 + (lane & 15);
                ldsm_x4(ah[mt], stb + swz2(arow, kc0));
            }
#pragma unroll
            for (int nt2 = 0; nt2 < 4; nt2++) {
                const uint32_t brow = wn * 64 + nt2 * 16 + (lane & 15);
                uint32_t bh[4];
                ldsm_x4(bh, stb + TILE2_B + swz2(brow, kc0));
#pragma unroll
                for (int mt = 0; mt < 2; mt++) {
                    mma_fp16(acc[mt][2 * nt2 + 0], ah[mt], bh[0], bh[2]);
                    mma_fp16(acc[mt][2 * nt2 + 1], ah[mt], bh[1], bh[3]);
                }
            }
        }
        s++; if (s == NST) s = 0;
    }

    // epilogue
#pragma unroll
    for (int mt = 0; mt < 2; mt++) {
        const int r = mBase + wm * 32 + mt * 16 + (lane >> 2);
#pragma unroll
        for (int nt = 0; nt < 8; nt++) {
            const int c = nBase + wn * 64 + nt * 8 + (lane & 3) * 2;
            const float2 bv = *(const float2*)(bias + c);
            float2 v0{acc[mt][nt][0] + bv.x, acc[mt][nt][1] + bv.y};
            float2 v1{acc[mt][nt][2] + bv.x, acc[mt][nt][3] + bv.y};
            *(float2*)(out + (size_t)r * OUTF + c)       = v0;
            *(float2*)(out + (size_t)(r + 8) * OUTF + c) = v1;
        }
    }
}

// ---------------- 2b. small fp16 GEMM (64x128, split-K) for loraA ----------
__global__ void __launch_bounds__(256, 2) gemm_small(
    const __half* __restrict__ Xh, const __half* __restrict__ Wh,
    float* __restrict__ outp)
{
    extern __shared__ __align__(128) char smem[];
    const uint32_t sb = smem_u32(smem);
    const int tid  = threadIdx.x;
    const int wid  = tid >> 5, lane = tid & 31;
    const int wm   = wid >> 1, wn = wid & 1;          // 4 x 2 warp grid, 16x64 tiles
    const int mBase = blockIdx.y * SBM;
    const int kz    = blockIdx.z;
    const int kt0   = kz * SKT;
    float* out = outp + (size_t)kz * NTOK * 128;

    const int kc = tid & 3;
    const int r0 = tid >> 2;                          // 0..63
    const uint32_t so_x  = swz(r0, kc);
    const uint32_t so_w0 = swz(r0, kc);
    const uint32_t so_w1 = swz(r0 + 64, kc);
    const __half* pX0 = Xh + (size_t)(mBase + r0) * INF + kc * 8;
    const __half* pW0 = Wh + (size_t)r0 * INF + kc * 8;
    const size_t RD = (size_t)64 * INF;

    float acc[8][4];
#pragma unroll
    for (int nt = 0; nt < 8; nt++)
#pragma unroll
        for (int q = 0; q < 4; q++) acc[nt][q] = 0.f;

#define SMALL_LOADS(kt, s) do {                                          \
        const uint32_t stb_ = sb + (uint32_t)(s) * SSTAGE_B;             \
        const int ko_ = (kt) * 32;                                       \
        cp16(stb_ + so_x, pX0 + ko_);                                    \
        cp16(stb_ + SXT_B + so_w0, pW0 + ko_);                           \
        cp16(stb_ + SXT_B + so_w1, pW0 + RD + ko_);                      \
        asm volatile("cp.async.commit_group;" ::: "memory");             \
    } while (0)

    SMALL_LOADS(kt0 + 0, 0);
    SMALL_LOADS(kt0 + 1, 1);
    SMALL_LOADS(kt0 + 2, 2);

    int s = 0;
    for (int kt = 0; kt < SKT; kt++) {
        if (kt + 2 < SKT)      asm volatile("cp.async.wait_group 2;" ::: "memory");
        else if (kt + 1 < SKT) asm volatile("cp.async.wait_group 1;" ::: "memory");
        else                   asm volatile("cp.async.wait_group 0;" ::: "memory");
        __syncthreads();

        if (kt + 3 < SKT) {
            int s2 = s + 3; if (s2 >= 4) s2 -= 4;
            SMALL_LOADS(kt0 + kt + 3, s2);
        }

        const uint32_t stb = sb + (uint32_t)s * SSTAGE_B;
#pragma unroll
        for (int ks = 0; ks < 2; ks++) {
            const uint32_t kc0 = ks * 2 + (lane >> 4);
            uint32_t ah[4];
            const uint32_t arow = wm * 16 + (lane & 15);
            ldsm_x4(ah, stb + swz(arow, kc0));
#pragma unroll
            for (int nt2 = 0; nt2 < 4; nt2++) {
                const uint32_t brow = wn * 64 + nt2 * 16 + (lane & 15);
                uint32_t bh[4];
                ldsm_x4(bh, stb + SXT_B + swz(brow, kc0));
                mma_fp16(acc[2 * nt2 + 0], ah, bh[0], bh[2]);
                mma_fp16(acc[2 * nt2 + 1], ah, bh[1], bh[3]);
            }
        }
        s++; if (s == 4) s = 0;
    }

    const int r = mBase + wm * 16 + (lane >> 2);
#pragma unroll
    for (int nt = 0; nt < 8; nt++) {
        const int c = wn * 64 + nt * 8 + (lane & 3) * 2;
        float2 v0{acc[nt][0], acc[nt][1]};
        float2 v1{acc[nt][2], acc[nt][3]};
        *(float2*)(out + (size_t)r * 128 + c)       = v0;
        *(float2*)(out + (size_t)(r + 8) * 128 + c) = v1;
    }
}

// ---------------- 3. gather + split-K reduce -> weighted coef ----------------
__global__ void __launch_bounds__(256) gather_kernel()
{
    const int gi = blockIdx.x * 256 + threadIdx.x;
    if (gi >= NTOK * 32) return;
    const int t  = gi >> 5;
    const int kr = gi & 31;
    const int kk = kr >> 4;
    const int r  = kr & 15;
    const int e  = g_idx[t * 2 + kk];
    const size_t off = (size_t)t * 128 + e * RANK + r;
    float v = g_interp[off]
            + g_interp[(size_t)1 * NTOK * 128 + off]
            + g_interp[(size_t)2 * NTOK * 128 + off]
            + g_interp[(size_t)3 * NTOK * 128 + off];
    g_coef[gi] = v * g_wts[t * 2 + kk];
}

// ---------------- 4. LoRA B apply ----------------
__global__ void __launch_bounds__(128) loraB_kernel(
    const float* __restrict__ Bw, float* __restrict__ out)
{
    const int o = blockIdx.x * 128 + threadIdx.x;
    const int tBase = blockIdx.y * 128;
    for (int tt = 0; tt < 128; tt++) {
        const int t = tBase + tt;
        const int e0 = g_idx[t * 2 + 0];
        const int e1 = g_idx[t * 2 + 1];
        const float4* b0 = (const float4*)(Bw + ((size_t)e0 * OUTF + o) * RANK);
        const float4* b1 = (const float4*)(Bw + ((size_t)e1 * OUTF + o) * RANK);
        const float4* c  = (const float4*)(g_coef + t * 32);
        float acc = 0.f;
#pragma unroll
        for (int q = 0; q < 4; q++) {
            float4 bv = b0[q]; float4 cv = c[q];
            acc += bv.x * cv.x + bv.y * cv.y + bv.z * cv.z + bv.w * cv.w;
        }
#pragma unroll
        for (int q = 0; q < 4; q++) {
            float4 bv = b1[q]; float4 cv = c[q + 4];
            acc += bv.x * cv.x + bv.y * cv.y + bv.z * cv.z + bv.w * cv.w;
        }
        out[(size_t)t * OUTF + o] += acc;
    }
}

// ---------------- launch ----------------
extern "C" void kernel_launch(void* const* d_in, const int* in_sizes, int n_in,
                              void* d_out, int out_size)
{
    const float* x   = (const float*)d_in[0];
    const float* Wb  = (const float*)d_in[1];
    const float* bb  = (const float*)d_in[2];
    const float* Wr  = (const float*)d_in[3];
    const float* Aw  = (const float*)d_in[4];
    const float* Bw  = (const float*)d_in[5];
    float* out = (float*)d_out;

    void *pXh, *pWh, *pAh, *pInterp;
    cudaGetSymbolAddress(&pXh, g_Xh);
    cudaGetSymbolAddress(&pWh, g_Wh);
    cudaGetSymbolAddress(&pAh, g_Ah);
    cudaGetSymbolAddress(&pInterp, g_interp);

    cudaFuncSetAttribute(gemm_mma,
                         cudaFuncAttributeMaxDynamicSharedMemorySize, SMEM_BIG);
    cudaFuncSetAttribute(gemm_small,
                         cudaFuncAttributeMaxDynamicSharedMemorySize, SMEM_SMALL);

    // W / A converts
    convert1_kernel<<<(OUTF * INF / 4 + 255) / 256, 256>>>(
        Wb, (__half*)pWh, OUTF * INF / 4);
    convert1_kernel<<<(NEXP * RANK * INF / 4 + 255) / 256, 256>>>(
        Aw, (__half*)pAh, NEXP * RANK * INF / 4);

    // fused router + x convert
    router_convert_kernel<<<NTOK, 256>>>(x, Wr, (__half*)pXh);

    // LoRA A as split-K skinny GEMM over all experts
    gemm_small<<<dim3(1, NTOK / SBM, SPLITK), 256, SMEM_SMALL>>>(
        (const __half*)pXh, (const __half*)pAh, (float*)pInterp);

    // gather + reduce + weight
    gather_kernel<<<(NTOK * 32 + 255) / 256, 256>>>();

    // base GEMM (128x128 tiles, BK=64, 2 CTA/SM)
    gemm_mma<<<dim3(OUTF / BN, NTOK / BM), 256, SMEM_BIG>>>(
        (const __half*)pXh, (const __half*)pWh, bb, out);

    // LoRA B
    loraB_kernel<<<dim3(OUTF / 128, NTOK / 128), 128>>>(Bw, out);
}

// round 11
// speedup vs baseline: 1.1556x; 1.0105x over previous
#include <cuda_runtime.h>
#include <cuda_fp16.h>
#include <cstdint>

// ---------------- problem constants ----------------
#define NTOK 8192
#define INF  4096
#define OUTF 4096
#define NEXP 8
#define RANK 16
// SCALING = 16/16 = 1.0

// ---------------- base GEMM config (BK=64, 3-stage) ----------------
#define BM 128
#define BN 128
#define BK2 64                   // fp16 per K-chunk (128B rows)
#define KT2 (INF / BK2)          // 64 iterations
#define NST 3
#define TILE2_B (128 * 128)      // 16384: 128 rows x 64 fp16
#define STAGE2_B (2 * TILE2_B)   // 32768
#define SMEM_BIG (NST * STAGE2_B)   // 98304

// ---------------- small GEMM config (loraA, split-K) ----------------
#define SBM 64
#define SBN 128
#define SPLITK 4
#define SKT (INF / 32 / SPLITK)  // 32 k-chunks of 32 per slice
#define SXT_B (SBM * 64)         // 4096
#define SWT_B (SBN * 64)         // 8192
#define SSTAGE_B (SXT_B + SWT_B) // 12288
#define SMEM_SMALL (4 * SSTAGE_B)   // 48 KB

// ---------------- scratch (device globals) ----------------
__device__ __half g_Xh[(size_t)NTOK * INF];
__device__ __half g_Wh[(size_t)OUTF * INF];
__device__ __half g_Ah[(size_t)NEXP * RANK * INF];        // all-expert A, fp16
__device__ float  g_interp[(size_t)SPLITK * NTOK * 128];  // split-K partials
__device__ int    g_idx [NTOK * 2];
__device__ float  g_wts [NTOK * 2];
__device__ float  g_coef[NTOK * 2 * RANK];

// ---------------- helpers ----------------
__device__ __forceinline__ uint32_t smem_u32(const void* p) {
    uint32_t a;
    asm("{ .reg .u64 t; cvta.to.shared.u64 t, %1; cvt.u32.u64 %0, t; }" : "=r"(a) : "l"(p));
    return a;
}
// 64B-row swizzle (4 chunks, 2-row period) — small GEMM
__device__ __forceinline__ uint32_t swz(uint32_t row, uint32_t kc) {
    return row * 64u + (((kc ^ (row >> 1)) & 3u) << 4);
}
// 128B-row swizzle (8 chunks, 8-row period) — base GEMM
__device__ __forceinline__ uint32_t swz2(uint32_t row, uint32_t kc) {
    return row * 128u + (((kc ^ row) & 7u) << 4);
}
__device__ __forceinline__ void ldsm_x4(uint32_t (&r)[4], uint32_t addr) {
    asm volatile("ldmatrix.sync.aligned.m8n8.x4.shared.b16 {%0,%1,%2,%3}, [%4];"
        : "=r"(r[0]), "=r"(r[1]), "=r"(r[2]), "=r"(r[3]) : "r"(addr));
}
__device__ __forceinline__ void mma_fp16(float (&c)[4], const uint32_t (&a)[4],
                                         uint32_t b0, uint32_t b1) {
    asm volatile("mma.sync.aligned.m16n8k16.row.col.f32.f16.f16.f32 "
        "{%0,%1,%2,%3}, {%4,%5,%6,%7}, {%8,%9}, {%0,%1,%2,%3};"
        : "+f"(c[0]), "+f"(c[1]), "+f"(c[2]), "+f"(c[3])
        : "r"(a[0]), "r"(a[1]), "r"(a[2]), "r"(a[3]), "r"(b0), "r"(b1));
}
__device__ __forceinline__ void cp16(uint32_t saddr, const void* gaddr) {
    asm volatile("cp.async.cg.shared.global [%0], [%1], 16;" :: "r"(saddr), "l"(gaddr));
}

// ---------------- 0. fp32 -> fp16 ----------------
__global__ void __launch_bounds__(256) convert1_kernel(
    const float* __restrict__ src, __half* __restrict__ hi, int n4)
{
    int i = blockIdx.x * 256 + threadIdx.x;
    if (i >= n4) return;
    float4 v = ((const float4*)src)[i];
    __half2 H01{__float2half(v.x), __float2half(v.y)};
    __half2 H23{__float2half(v.z), __float2half(v.w)};
    uint2 H{*(uint32_t*)&H01, *(uint32_t*)&H23};
    ((uint2*)hi)[i] = H;
}

// ---------------- 1. router (standalone, float4) ----------------
__global__ void __launch_bounds__(256) router_kernel(
    const float* __restrict__ x, const float* __restrict__ Wr)
{
    const int t = blockIdx.x;
    const float4* xt = (const float4*)(x + (size_t)t * INF);
    const float4* wr = (const float4*)Wr;

    float acc[NEXP];
#pragma unroll
    for (int e = 0; e < NEXP; e++) acc[e] = 0.f;
#pragma unroll 4
    for (int i = threadIdx.x; i < INF / 4; i += 256) {
        float4 xv = xt[i];
#pragma unroll
        for (int e = 0; e < NEXP; e++) {
            float4 wv = wr[e * (INF / 4) + i];
            acc[e] += xv.x * wv.x + xv.y * wv.y + xv.z * wv.z + xv.w * wv.w;
        }
    }
#pragma unroll
    for (int e = 0; e < NEXP; e++)
#pragma unroll
        for (int off = 16; off > 0; off >>= 1)
            acc[e] += __shfl_down_sync(0xffffffffu, acc[e], off);

    __shared__ float sred[NEXP][8];
    const int warp = threadIdx.x >> 5, lane = threadIdx.x & 31;
    if (lane == 0)
#pragma unroll
        for (int e = 0; e < NEXP; e++) sred[e][warp] = acc[e];
    __syncthreads();

    if (threadIdx.x == 0) {
        float logit[NEXP];
#pragma unroll
        for (int e = 0; e < NEXP; e++) {
            float s = 0.f;
#pragma unroll
            for (int w = 0; w < 8; w++) s += sred[e][w];
            logit[e] = s;
        }
        int i0 = 0;
#pragma unroll
        for (int e = 1; e < NEXP; e++) if (logit[e] > logit[i0]) i0 = e;
        int i1 = (i0 == 0) ? 1 : 0;
#pragma unroll
        for (int e = 0; e < NEXP; e++) {
            if (e == i0) continue;
            if (logit[e] > logit[i1]) i1 = e;
        }
        const float e1 = expf(logit[i1] - logit[i0]);
        const float inv = 1.f / (1.f + e1);
        g_idx[t * 2 + 0] = i0;  g_idx[t * 2 + 1] = i1;
        g_wts[t * 2 + 0] = inv; g_wts[t * 2 + 1] = e1 * inv;
    }
}

// ---------------- 2a. base fp16 GEMM (128x128, BK=64, 3-stage, 2 CTA/SM) ----
__global__ void __launch_bounds__(256, 2) gemm_mma(
    const __half* __restrict__ Xh, const __half* __restrict__ Wh,
    const float* __restrict__ bias, float* __restrict__ out)
{
    extern __shared__ __align__(128) char smem[];
    const uint32_t sb = smem_u32(smem);
    const int tid  = threadIdx.x;
    const int wid  = tid >> 5, lane = tid & 31;
    const int wm   = wid >> 1, wn = wid & 1;          // 4 x 2 warp grid
    const int mBase = blockIdx.y * BM;
    const int nBase = blockIdx.x * BN;

    const int lr = tid >> 3;                          // 0..31
    const int lc = tid & 7;                           // chunk 0..7
    const __half* pX0 = Xh + (size_t)(mBase + lr) * INF + lc * 8;
    const __half* pW0 = Wh + (size_t)(nBase + lr) * INF + lc * 8;
    const size_t R32 = (size_t)32 * INF;
    const uint32_t sx0 = swz2(lr,      lc);
    const uint32_t sx1 = swz2(lr + 32, lc);
    const uint32_t sx2 = swz2(lr + 64, lc);
    const uint32_t sx3 = swz2(lr + 96, lc);

    float acc[2][8][4];
#pragma unroll
    for (int mt = 0; mt < 2; mt++)
#pragma unroll
        for (int nt = 0; nt < 8; nt++)
#pragma unroll
            for (int q = 0; q < 4; q++) acc[mt][nt][q] = 0.f;

#define BIG_LOADS(kt, s) do {                                            \
        const uint32_t stb_ = sb + (uint32_t)(s) * STAGE2_B;             \
        const int ko_ = (kt) * BK2;                                      \
        cp16(stb_ + sx0, pX0 + ko_);                                     \
        cp16(stb_ + sx1, pX0 + R32 + ko_);                               \
        cp16(stb_ + sx2, pX0 + 2 * R32 + ko_);                           \
        cp16(stb_ + sx3, pX0 + 3 * R32 + ko_);                           \
        cp16(stb_ + TILE2_B + sx0, pW0 + ko_);                           \
        cp16(stb_ + TILE2_B + sx1, pW0 + R32 + ko_);                     \
        cp16(stb_ + TILE2_B + sx2, pW0 + 2 * R32 + ko_);                 \
        cp16(stb_ + TILE2_B + sx3, pW0 + 3 * R32 + ko_);                 \
        asm volatile("cp.async.commit_group;" ::: "memory");             \
    } while (0)

    BIG_LOADS(0, 0);
    BIG_LOADS(1, 1);

    int s = 0;
    for (int kt = 0; kt < KT2; kt++) {
        if (kt + 1 < KT2) asm volatile("cp.async.wait_group 1;" ::: "memory");
        else              asm volatile("cp.async.wait_group 0;" ::: "memory");
        __syncthreads();

        if (kt + 2 < KT2) {
            int s2 = s + 2; if (s2 >= NST) s2 -= NST;
            BIG_LOADS(kt + 2, s2);
        }

        const uint32_t stb = sb + (uint32_t)s * STAGE2_B;
#pragma unroll
        for (int ks = 0; ks < 4; ks++) {
            const uint32_t kc0 = ks * 2 + (lane >> 4);
            uint32_t ah[2][4];
#pragma unroll
            for (int mt = 0; mt < 2; mt++) {
                const uint32_t arow = wm * 32 + mt * 16 + (lane & 15);
                ldsm_x4(ah[mt], stb + swz2(arow, kc0));
            }
#pragma unroll
            for (int nt2 = 0; nt2 < 4; nt2++) {
                const uint32_t brow = wn * 64 + nt2 * 16 + (lane & 15);
                uint32_t bh[4];
                ldsm_x4(bh, stb + TILE2_B + swz2(brow, kc0));
#pragma unroll
                for (int mt = 0; mt < 2; mt++) {
                    mma_fp16(acc[mt][2 * nt2 + 0], ah[mt], bh[0], bh[2]);
                    mma_fp16(acc[mt][2 * nt2 + 1], ah[mt], bh[1], bh[3]);
                }
            }
        }
        s++; if (s == NST) s = 0;
    }

#pragma unroll
    for (int mt = 0; mt < 2; mt++) {
        const int r = mBase + wm * 32 + mt * 16 + (lane >> 2);
#pragma unroll
        for (int nt = 0; nt < 8; nt++) {
            const int c = nBase + wn * 64 + nt * 8 + (lane & 3) * 2;
            const float2 bv = *(const float2*)(bias + c);
            float2 v0{acc[mt][nt][0] + bv.x, acc[mt][nt][1] + bv.y};
            float2 v1{acc[mt][nt][2] + bv.x, acc[mt][nt][3] + bv.y};
            *(float2*)(out + (size_t)r * OUTF + c)       = v0;
            *(float2*)(out + (size_t)(r + 8) * OUTF + c) = v1;
        }
    }
}

// ---------------- 2b. small fp16 GEMM (64x128, split-K) for loraA ----------
__global__ void __launch_bounds__(256, 2) gemm_small(
    const __half* __restrict__ Xh, const __half* __restrict__ Wh,
    float* __restrict__ outp)
{
    extern __shared__ __align__(128) char smem[];
    const uint32_t sb = smem_u32(smem);
    const int tid  = threadIdx.x;
    const int wid  = tid >> 5, lane = tid & 31;
    const int wm   = wid >> 1, wn = wid & 1;
    const int mBase = blockIdx.y * SBM;
    const int kz    = blockIdx.z;
    const int kt0   = kz * SKT;
    float* out = outp + (size_t)kz * NTOK * 128;

    const int kc = tid & 3;
    const int r0 = tid >> 2;
    const uint32_t so_x  = swz(r0, kc);
    const uint32_t so_w0 = swz(r0, kc);
    const uint32_t so_w1 = swz(r0 + 64, kc);
    const __half* pX0 = Xh + (size_t)(mBase + r0) * INF + kc * 8;
    const __half* pW0 = Wh + (size_t)r0 * INF + kc * 8;
    const size_t RD = (size_t)64 * INF;

    float acc[8][4];
#pragma unroll
    for (int nt = 0; nt < 8; nt++)
#pragma unroll
        for (int q = 0; q < 4; q++) acc[nt][q] = 0.f;

#define SMALL_LOADS(kt, s) do {                                          \
        const uint32_t stb_ = sb + (uint32_t)(s) * SSTAGE_B;             \
        const int ko_ = (kt) * 32;                                       \
        cp16(stb_ + so_x, pX0 + ko_);                                    \
        cp16(stb_ + SXT_B + so_w0, pW0 + ko_);                           \
        cp16(stb_ + SXT_B + so_w1, pW0 + RD + ko_);                      \
        asm volatile("cp.async.commit_group;" ::: "memory");             \
    } while (0)

    SMALL_LOADS(kt0 + 0, 0);
    SMALL_LOADS(kt0 + 1, 1);
    SMALL_LOADS(kt0 + 2, 2);

    int s = 0;
    for (int kt = 0; kt < SKT; kt++) {
        if (kt + 2 < SKT)      asm volatile("cp.async.wait_group 2;" ::: "memory");
        else if (kt + 1 < SKT) asm volatile("cp.async.wait_group 1;" ::: "memory");
        else                   asm volatile("cp.async.wait_group 0;" ::: "memory");
        __syncthreads();

        if (kt + 3 < SKT) {
            int s2 = s + 3; if (s2 >= 4) s2 -= 4;
            SMALL_LOADS(kt0 + kt + 3, s2);
        }

        const uint32_t stb = sb + (uint32_t)s * SSTAGE_B;
#pragma unroll
        for (int ks = 0; ks < 2; ks++) {
            const uint32_t kc0 = ks * 2 + (lane >> 4);
            uint32_t ah[4];
            const uint32_t arow = wm * 16 + (lane & 15);
            ldsm_x4(ah, stb + swz(arow, kc0));
#pragma unroll
            for (int nt2 = 0; nt2 < 4; nt2++) {
                const uint32_t brow = wn * 64 + nt2 * 16 + (lane & 15);
                uint32_t bh[4];
                ldsm_x4(bh, stb + SXT_B + swz(brow, kc0));
                mma_fp16(acc[2 * nt2 + 0], ah, bh[0], bh[2]);
                mma_fp16(acc[2 * nt2 + 1], ah, bh[1], bh[3]);
            }
        }
        s++; if (s == 4) s = 0;
    }

    const int r = mBase + wm * 16 + (lane >> 2);
#pragma unroll
    for (int nt = 0; nt < 8; nt++) {
        const int c = wn * 64 + nt * 8 + (lane & 3) * 2;
        float2 v0{acc[nt][0], acc[nt][1]};
        float2 v1{acc[nt][2], acc[nt][3]};
        *(float2*)(out + (size_t)r * 128 + c)       = v0;
        *(float2*)(out + (size_t)(r + 8) * 128 + c) = v1;
    }
}

// ---------------- 3. gather + split-K reduce -> weighted coef ----------------
__global__ void __launch_bounds__(256) gather_kernel()
{
    const int gi = blockIdx.x * 256 + threadIdx.x;
    if (gi >= NTOK * 32) return;
    const int t  = gi >> 5;
    const int kr = gi & 31;
    const int kk = kr >> 4;
    const int r  = kr & 15;
    const int e  = g_idx[t * 2 + kk];
    const size_t off = (size_t)t * 128 + e * RANK + r;
    float v = g_interp[off]
            + g_interp[(size_t)1 * NTOK * 128 + off]
            + g_interp[(size_t)2 * NTOK * 128 + off]
            + g_interp[(size_t)3 * NTOK * 128 + off];
    g_coef[gi] = v * g_wts[t * 2 + kk];
}

// ---------------- 4. LoRA B apply ----------------
__global__ void __launch_bounds__(128) loraB_kernel(
    const float* __restrict__ Bw, float* __restrict__ out)
{
    const int o = blockIdx.x * 128 + threadIdx.x;
    const int tBase = blockIdx.y * 128;
    for (int tt = 0; tt < 128; tt++) {
        const int t = tBase + tt;
        const int e0 = g_idx[t * 2 + 0];
        const int e1 = g_idx[t * 2 + 1];
        const float4* b0 = (const float4*)(Bw + ((size_t)e0 * OUTF + o) * RANK);
        const float4* b1 = (const float4*)(Bw + ((size_t)e1 * OUTF + o) * RANK);
        const float4* c  = (const float4*)(g_coef + t * 32);
        float acc = 0.f;
#pragma unroll
        for (int q = 0; q < 4; q++) {
            float4 bv = b0[q]; float4 cv = c[q];
            acc += bv.x * cv.x + bv.y * cv.y + bv.z * cv.z + bv.w * cv.w;
        }
#pragma unroll
        for (int q = 0; q < 4; q++) {
            float4 bv = b1[q]; float4 cv = c[q + 4];
            acc += bv.x * cv.x + bv.y * cv.y + bv.z * cv.z + bv.w * cv.w;
        }
        out[(size_t)t * OUTF + o] += acc;
    }
}

// ---------------- launch (stream-forked for graph concurrency) ----------------
extern "C" void kernel_launch(void* const* d_in, const int* in_sizes, int n_in,
                              void* d_out, int out_size)
{
    const float* x   = (const float*)d_in[0];
    const float* Wb  = (const float*)d_in[1];
    const float* bb  = (const float*)d_in[2];
    const float* Wr  = (const float*)d_in[3];
    const float* Aw  = (const float*)d_in[4];
    const float* Bw  = (const float*)d_in[5];
    float* out = (float*)d_out;

    void *pXh, *pWh, *pAh, *pInterp;
    cudaGetSymbolAddress(&pXh, g_Xh);
    cudaGetSymbolAddress(&pWh, g_Wh);
    cudaGetSymbolAddress(&pAh, g_Ah);
    cudaGetSymbolAddress(&pInterp, g_interp);

    cudaFuncSetAttribute(gemm_mma,
                         cudaFuncAttributeMaxDynamicSharedMemorySize, SMEM_BIG);
    cudaFuncSetAttribute(gemm_small,
                         cudaFuncAttributeMaxDynamicSharedMemorySize, SMEM_SMALL);

    // one-time stream/event setup (infrastructure, not work)
    static cudaStream_t s1 = [] {
        cudaStream_t s; cudaStreamCreateWithFlags(&s, cudaStreamNonBlocking); return s;
    }();
    static cudaStream_t s2 = [] {
        cudaStream_t s; cudaStreamCreateWithFlags(&s, cudaStreamNonBlocking); return s;
    }();
    static cudaEvent_t evRoot = [] {
        cudaEvent_t e; cudaEventCreateWithFlags(&e, cudaEventDisableTiming); return e;
    }();
    static cudaEvent_t evW = [] {
        cudaEvent_t e; cudaEventCreateWithFlags(&e, cudaEventDisableTiming); return e;
    }();
    static cudaEvent_t evX = [] {
        cudaEvent_t e; cudaEventCreateWithFlags(&e, cudaEventDisableTiming); return e;
    }();
    static cudaEvent_t evG = [] {
        cudaEvent_t e; cudaEventCreateWithFlags(&e, cudaEventDisableTiming); return e;
    }();

    // fork side streams off the main (capture) stream
    cudaEventRecord(evRoot, 0);
    cudaStreamWaitEvent(s1, evRoot, 0);
    cudaStreamWaitEvent(s2, evRoot, 0);

    // s1: W convert
    convert1_kernel<<<(OUTF * INF / 4 + 255) / 256, 256, 0, s1>>>(
        Wb, (__half*)pWh, OUTF * INF / 4);
    cudaEventRecord(evW, s1);

    // s2: router (fp32 x only) + A convert
    router_kernel<<<NTOK, 256, 0, s2>>>(x, Wr);
    convert1_kernel<<<(NEXP * RANK * INF / 4 + 255) / 256, 256, 0, s2>>>(
        Aw, (__half*)pAh, NEXP * RANK * INF / 4);

    // main: x convert
    convert1_kernel<<<(NTOK * INF / 4 + 255) / 256, 256>>>(
        x, (__half*)pXh, NTOK * INF / 4);
    cudaEventRecord(evX, 0);

    // s2: loraA GEMM (needs Xh) + gather
    cudaStreamWaitEvent(s2, evX, 0);
    gemm_small<<<dim3(1, NTOK / SBM, SPLITK), 256, SMEM_SMALL, s2>>>(
        (const __half*)pXh, (const __half*)pAh, (float*)pInterp);
    gather_kernel<<<(NTOK * 32 + 255) / 256, 256, 0, s2>>>();
    cudaEventRecord(evG, s2);

    // main: base GEMM (needs Wh) then loraB (needs gather + out)
    cudaStreamWaitEvent(0, evW, 0);
    gemm_mma<<<dim3(OUTF / BN, NTOK / BM), 256, SMEM_BIG>>>(
        (const __half*)pXh, (const __half*)pWh, bb, out);
    cudaStreamWaitEvent(0, evG, 0);
    loraB_kernel<<<dim3(OUTF / 128, NTOK / 128), 128>>>(Bw, out);
}

// round 14
// speedup vs baseline: 1.6332x; 1.4133x over previous
#include <cuda_runtime.h>
#include <cuda_fp16.h>
#include <cstdint>

// ---------------- problem constants ----------------
#define NTOK 8192
#define INF  4096
#define OUTF 4096
#define NEXP 8
#define RANK 16
// SCALING = 16/16 = 1.0

// ---------------- base GEMM config (BK=64, 3-stage) ----------------
#define BM 128
#define BN 128
#define BK2 64                   // fp16 per K-chunk (128B rows)
#define KT2 (INF / BK2)          // 64 iterations
#define NST 3
#define TILE2_B (128 * 128)      // 16384: 128 rows x 64 fp16
#define STAGE2_B (2 * TILE2_B)   // 32768
#define SMEM_BIG (NST * STAGE2_B)   // 98304

// ---------------- small GEMM config (loraA, split-K) ----------------
#define SBM 64
#define SBN 128
#define SPLITK 4
#define SKT (INF / 32 / SPLITK)  // 32 k-chunks of 32 per slice
#define SXT_B (SBM * 64)         // 4096
#define SWT_B (SBN * 64)         // 8192
#define SSTAGE_B (SXT_B + SWT_B) // 12288
#define SMEM_SMALL (4 * SSTAGE_B)   // 48 KB

// ---------------- scratch (device globals) ----------------
__device__ __half g_Xh[(size_t)NTOK * INF];
__device__ __half g_Wh[(size_t)OUTF * INF];
__device__ __half g_Ah[(size_t)NEXP * RANK * INF];        // all-expert A, fp16
__device__ __half g_Bh[(size_t)NEXP * OUTF * RANK];       // B weights, fp16
__device__ float  g_interp[(size_t)SPLITK * NTOK * 128];  // split-K partials
__device__ int    g_idx [NTOK * 2];
__device__ float  g_wts [NTOK * 2];
__device__ __half g_coefh[NTOK * 2 * RANK];               // weighted coef, fp16

// ---------------- helpers ----------------
__device__ __forceinline__ uint32_t smem_u32(const void* p) {
    uint32_t a;
    asm("{ .reg .u64 t; cvta.to.shared.u64 t, %1; cvt.u32.u64 %0, t; }" : "=r"(a) : "l"(p));
    return a;
}
// 64B-row swizzle (4 chunks, 2-row period) — small GEMM
__device__ __forceinline__ uint32_t swz(uint32_t row, uint32_t kc) {
    return row * 64u + (((kc ^ (row >> 1)) & 3u) << 4);
}
// 128B-row swizzle (8 chunks, 8-row period) — base GEMM
__device__ __forceinline__ uint32_t swz2(uint32_t row, uint32_t kc) {
    return row * 128u + (((kc ^ row) & 7u) << 4);
}
__device__ __forceinline__ void ldsm_x4(uint32_t (&r)[4], uint32_t addr) {
    asm volatile("ldmatrix.sync.aligned.m8n8.x4.shared.b16 {%0,%1,%2,%3}, [%4];"
        : "=r"(r[0]), "=r"(r[1]), "=r"(r[2]), "=r"(r[3]) : "r"(addr));
}
__device__ __forceinline__ void mma_fp16(float (&c)[4], const uint32_t (&a)[4],
                                         uint32_t b0, uint32_t b1) {
    asm volatile("mma.sync.aligned.m16n8k16.row.col.f32.f16.f16.f32 "
        "{%0,%1,%2,%3}, {%4,%5,%6,%7}, {%8,%9}, {%0,%1,%2,%3};"
        : "+f"(c[0]), "+f"(c[1]), "+f"(c[2]), "+f"(c[3])
        : "r"(a[0]), "r"(a[1]), "r"(a[2]), "r"(a[3]), "r"(b0), "r"(b1));
}
__device__ __forceinline__ void cp16(uint32_t saddr, const void* gaddr) {
    asm volatile("cp.async.cg.shared.global [%0], [%1], 16;" :: "r"(saddr), "l"(gaddr));
}

// ---------------- 0. fp32 -> fp16 (8 elems/thread, 16B stores) ----------------
__global__ void __launch_bounds__(256) convert1_kernel(
    const float* __restrict__ src, __half* __restrict__ hi, int n8)
{
    int i = blockIdx.x * 256 + threadIdx.x;
    if (i >= n8) return;
    const float4* s4 = (const float4*)src;
    float4 a = s4[2 * i], b = s4[2 * i + 1];
    __half2 h0 = __floats2half2_rn(a.x, a.y);
    __half2 h1 = __floats2half2_rn(a.z, a.w);
    __half2 h2 = __floats2half2_rn(b.x, b.y);
    __half2 h3 = __floats2half2_rn(b.z, b.w);
    uint4 H{*(uint32_t*)&h0, *(uint32_t*)&h1, *(uint32_t*)&h2, *(uint32_t*)&h3};
    ((uint4*)hi)[i] = H;
}

// ---------------- 1. router (standalone, float4) ----------------
__global__ void __launch_bounds__(256) router_kernel(
    const float* __restrict__ x, const float* __restrict__ Wr)
{
    const int t = blockIdx.x;
    const float4* xt = (const float4*)(x + (size_t)t * INF);
    const float4* wr = (const float4*)Wr;

    float acc[NEXP];
#pragma unroll
    for (int e = 0; e < NEXP; e++) acc[e] = 0.f;
#pragma unroll 4
    for (int i = threadIdx.x; i < INF / 4; i += 256) {
        float4 xv = xt[i];
#pragma unroll
        for (int e = 0; e < NEXP; e++) {
            float4 wv = wr[e * (INF / 4) + i];
            acc[e] += xv.x * wv.x + xv.y * wv.y + xv.z * wv.z + xv.w * wv.w;
        }
    }
#pragma unroll
    for (int e = 0; e < NEXP; e++)
#pragma unroll
        for (int off = 16; off > 0; off >>= 1)
            acc[e] += __shfl_down_sync(0xffffffffu, acc[e], off);

    __shared__ float sred[NEXP][8];
    const int warp = threadIdx.x >> 5, lane = threadIdx.x & 31;
    if (lane == 0)
#pragma unroll
        for (int e = 0; e < NEXP; e++) sred[e][warp] = acc[e];
    __syncthreads();

    if (threadIdx.x == 0) {
        float logit[NEXP];
#pragma unroll
        for (int e = 0; e < NEXP; e++) {
            float s = 0.f;
#pragma unroll
            for (int w = 0; w < 8; w++) s += sred[e][w];
            logit[e] = s;
        }
        int i0 = 0;
#pragma unroll
        for (int e = 1; e < NEXP; e++) if (logit[e] > logit[i0]) i0 = e;
        int i1 = (i0 == 0) ? 1 : 0;
#pragma unroll
        for (int e = 0; e < NEXP; e++) {
            if (e == i0) continue;
            if (logit[e] > logit[i1]) i1 = e;
        }
        const float e1 = expf(logit[i1] - logit[i0]);
        const float inv = 1.f / (1.f + e1);
        g_idx[t * 2 + 0] = i0;  g_idx[t * 2 + 1] = i1;
        g_wts[t * 2 + 0] = inv; g_wts[t * 2 + 1] = e1 * inv;
    }
}

// ---------------- 2a. base fp16 GEMM (128x128, BK=64, 3-stage, 2 CTA/SM) ----
__global__ void __launch_bounds__(256, 2) gemm_mma(
    const __half* __restrict__ Xh, const __half* __restrict__ Wh,
    const float* __restrict__ bias, float* __restrict__ out)
{
    extern __shared__ __align__(128) char smem[];
    const uint32_t sb = smem_u32(smem);
    const int tid  = threadIdx.x;
    const int wid  = tid >> 5, lane = tid & 31;
    const int wm   = wid >> 1, wn = wid & 1;          // 4 x 2 warp grid
    const int mBase = blockIdx.y * BM;
    const int nBase = blockIdx.x * BN;

    const int lr = tid >> 3;                          // 0..31
    const int lc = tid & 7;                           // chunk 0..7
    const __half* pX0 = Xh + (size_t)(mBase + lr) * INF + lc * 8;
    const __half* pW0 = Wh + (size_t)(nBase + lr) * INF + lc * 8;
    const size_t R32 = (size_t)32 * INF;
    const uint32_t sx0 = swz2(lr,      lc);
    const uint32_t sx1 = swz2(lr + 32, lc);
    const uint32_t sx2 = swz2(lr + 64, lc);
    const uint32_t sx3 = swz2(lr + 96, lc);

    float acc[2][8][4];
#pragma unroll
    for (int mt = 0; mt < 2; mt++)
#pragma unroll
        for (int nt = 0; nt < 8; nt++)
#pragma unroll
            for (int q = 0; q < 4; q++) acc[mt][nt][q] = 0.f;

#define BIG_LOADS(kt, s) do {                                            \
        const uint32_t stb_ = sb + (uint32_t)(s) * STAGE2_B;             \
        const int ko_ = (kt) * BK2;                                      \
        cp16(stb_ + sx0, pX0 + ko_);                                     \
        cp16(stb_ + sx1, pX0 + R32 + ko_);                               \
        cp16(stb_ + sx2, pX0 + 2 * R32 + ko_);                           \
        cp16(stb_ + sx3, pX0 + 3 * R32 + ko_);                           \
        cp16(stb_ + TILE2_B + sx0, pW0 + ko_);                           \
        cp16(stb_ + TILE2_B + sx1, pW0 + R32 + ko_);                     \
        cp16(stb_ + TILE2_B + sx2, pW0 + 2 * R32 + ko_);                 \
        cp16(stb_ + TILE2_B + sx3, pW0 + 3 * R32 + ko_);                 \
        asm volatile("cp.async.commit_group;" ::: "memory");             \
    } while (0)

    BIG_LOADS(0, 0);
    BIG_LOADS(1, 1);

    int s = 0;
    for (int kt = 0; kt < KT2; kt++) {
        if (kt + 1 < KT2) asm volatile("cp.async.wait_group 1;" ::: "memory");
        else              asm volatile("cp.async.wait_group 0;" ::: "memory");
        __syncthreads();

        if (kt + 2 < KT2) {
            int s2 = s + 2; if (s2 >= NST) s2 -= NST;
            BIG_LOADS(kt + 2, s2);
        }

        const uint32_t stb = sb + (uint32_t)s * STAGE2_B;
#pragma unroll
        for (int ks = 0; ks < 4; ks++) {
            const uint32_t kc0 = ks * 2 + (lane >> 4);
            uint32_t ah[2][4];
#pragma unroll
            for (int mt = 0; mt < 2; mt++) {
                const uint32_t arow = wm * 32 + mt * 16 + (lane & 15);
                ldsm_x4(ah[mt], stb + swz2(arow, kc0));
            }
#pragma unroll
            for (int nt2 = 0; nt2 < 4; nt2++) {
                const uint32_t brow = wn * 64 + nt2 * 16 + (lane & 15);
                uint32_t bh[4];
                ldsm_x4(bh, stb + TILE2_B + swz2(brow, kc0));
#pragma unroll
                for (int mt = 0; mt < 2; mt++) {
                    mma_fp16(acc[mt][2 * nt2 + 0], ah[mt], bh[0], bh[2]);
                    mma_fp16(acc[mt][2 * nt2 + 1], ah[mt], bh[1], bh[3]);
                }
            }
        }
        s++; if (s == NST) s = 0;
    }

#pragma unroll
    for (int mt = 0; mt < 2; mt++) {
        const int r = mBase + wm * 32 + mt * 16 + (lane >> 2);
#pragma unroll
        for (int nt = 0; nt < 8; nt++) {
            const int c = nBase + wn * 64 + nt * 8 + (lane & 3) * 2;
            const float2 bv = *(const float2*)(bias + c);
            float2 v0{acc[mt][nt][0] + bv.x, acc[mt][nt][1] + bv.y};
            float2 v1{acc[mt][nt][2] + bv.x, acc[mt][nt][3] + bv.y};
            *(float2*)(out + (size_t)r * OUTF + c)       = v0;
            *(float2*)(out + (size_t)(r + 8) * OUTF + c) = v1;
        }
    }
}

// ---------------- 2b. small fp16 GEMM (64x128, split-K) for loraA ----------
__global__ void __launch_bounds__(256, 2) gemm_small(
    const __half* __restrict__ Xh, const __half* __restrict__ Wh,
    float* __restrict__ outp)
{
    extern __shared__ __align__(128) char smem[];
    const uint32_t sb = smem_u32(smem);
    const int tid  = threadIdx.x;
    const int wid  = tid >> 5, lane = tid & 31;
    const int wm   = wid >> 1, wn = wid & 1;
    const int mBase = blockIdx.y * SBM;
    const int kz    = blockIdx.z;
    const int kt0   = kz * SKT;
    float* out = outp + (size_t)kz * NTOK * 128;

    const int kc = tid & 3;
    const int r0 = tid >> 2;
    const uint32_t so_x  = swz(r0, kc);
    const uint32_t so_w0 = swz(r0, kc);
    const uint32_t so_w1 = swz(r0 + 64, kc);
    const __half* pX0 = Xh + (size_t)(mBase + r0) * INF + kc * 8;
    const __half* pW0 = Wh + (size_t)r0 * INF + kc * 8;
    const size_t RD = (size_t)64 * INF;

    float acc[8][4];
#pragma unroll
    for (int nt = 0; nt < 8; nt++)
#pragma unroll
        for (int q = 0; q < 4; q++) acc[nt][q] = 0.f;

#define SMALL_LOADS(kt, s) do {                                          \
        const uint32_t stb_ = sb + (uint32_t)(s) * SSTAGE_B;             \
        const int ko_ = (kt) * 32;                                       \
        cp16(stb_ + so_x, pX0 + ko_);                                    \
        cp16(stb_ + SXT_B + so_w0, pW0 + ko_);                           \
        cp16(stb_ + SXT_B + so_w1, pW0 + RD + ko_);                      \
        asm volatile("cp.async.commit_group;" ::: "memory");             \
    } while (0)

    SMALL_LOADS(kt0 + 0, 0);
    SMALL_LOADS(kt0 + 1, 1);
    SMALL_LOADS(kt0 + 2, 2);

    int s = 0;
    for (int kt = 0; kt < SKT; kt++) {
        if (kt + 2 < SKT)      asm volatile("cp.async.wait_group 2;" ::: "memory");
        else if (kt + 1 < SKT) asm volatile("cp.async.wait_group 1;" ::: "memory");
        else                   asm volatile("cp.async.wait_group 0;" ::: "memory");
        __syncthreads();

        if (kt + 3 < SKT) {
            int s2 = s + 3; if (s2 >= 4) s2 -= 4;
            SMALL_LOADS(kt0 + kt + 3, s2);
        }

        const uint32_t stb = sb + (uint32_t)s * SSTAGE_B;
#pragma unroll
        for (int ks = 0; ks < 2; ks++) {
            const uint32_t kc0 = ks * 2 + (lane >> 4);
            uint32_t ah[4];
            const uint32_t arow = wm * 16 + (lane & 15);
            ldsm_x4(ah, stb + swz(arow, kc0));
#pragma unroll
            for (int nt2 = 0; nt2 < 4; nt2++) {
                const uint32_t brow = wn * 64 + nt2 * 16 + (lane & 15);
                uint32_t bh[4];
                ldsm_x4(bh, stb + SXT_B + swz(brow, kc0));
                mma_fp16(acc[2 * nt2 + 0], ah, bh[0], bh[2]);
                mma_fp16(acc[2 * nt2 + 1], ah, bh[1], bh[3]);
            }
        }
        s++; if (s == 4) s = 0;
    }

    const int r = mBase + wm * 16 + (lane >> 2);
#pragma unroll
    for (int nt = 0; nt < 8; nt++) {
        const int c = wn * 64 + nt * 8 + (lane & 3) * 2;
        float2 v0{acc[nt][0], acc[nt][1]};
        float2 v1{acc[nt][2], acc[nt][3]};
        *(float2*)(out + (size_t)r * 128 + c)       = v0;
        *(float2*)(out + (size_t)(r + 8) * 128 + c) = v1;
    }
}

// ---------------- 3. gather + split-K reduce -> weighted fp16 coef ----------
__global__ void __launch_bounds__(256) gather_kernel()
{
    const int gi = blockIdx.x * 256 + threadIdx.x;
    if (gi >= NTOK * 32) return;
    const int t  = gi >> 5;
    const int kr = gi & 31;
    const int kk = kr >> 4;
    const int r  = kr & 15;
    const int e  = g_idx[t * 2 + kk];
    const size_t off = (size_t)t * 128 + e * RANK + r;
    float v = g_interp[off]
            + g_interp[(size_t)1 * NTOK * 128 + off]
            + g_interp[(size_t)2 * NTOK * 128 + off]
            + g_interp[(size_t)3 * NTOK * 128 + off];
    g_coefh[gi] = __float2half(v * g_wts[t * 2 + kk]);
}

// ---------------- 4. LoRA B apply (HFMA2) ----------------
__global__ void __launch_bounds__(128) loraB_kernel(
    const __half* __restrict__ Bh, float* __restrict__ out)
{
    const int o = blockIdx.x * 128 + threadIdx.x;
    const int tBase = blockIdx.y * 128;
    for (int tt = 0; tt < 128; tt++) {
        const int t = tBase + tt;
        const int e0 = g_idx[t * 2 + 0];
        const int e1 = g_idx[t * 2 + 1];
        const uint4* b0 = (const uint4*)(Bh + ((size_t)e0 * OUTF + o) * RANK);
        const uint4* b1 = (const uint4*)(Bh + ((size_t)e1 * OUTF + o) * RANK);
        const uint4* ch = (const uint4*)(g_coefh + t * 32);

        __half2 acc = __floats2half2_rn(0.f, 0.f);
        uint4 bv, cv;
#pragma unroll
        for (int q = 0; q < 2; q++) {
            bv = b0[q]; cv = ch[q];
            acc = __hfma2(*(__half2*)&bv.x, *(__half2*)&cv.x, acc);
            acc = __hfma2(*(__half2*)&bv.y, *(__half2*)&cv.y, acc);
            acc = __hfma2(*(__half2*)&bv.z, *(__half2*)&cv.z, acc);
            acc = __hfma2(*(__half2*)&bv.w, *(__half2*)&cv.w, acc);
        }
#pragma unroll
        for (int q = 0; q < 2; q++) {
            bv = b1[q]; cv = ch[q + 2];
            acc = __hfma2(*(__half2*)&bv.x, *(__half2*)&cv.x, acc);
            acc = __hfma2(*(__half2*)&bv.y, *(__half2*)&cv.y, acc);
            acc = __hfma2(*(__half2*)&bv.z, *(__half2*)&cv.z, acc);
            acc = __hfma2(*(__half2*)&bv.w, *(__half2*)&cv.w, acc);
        }
        out[(size_t)t * OUTF + o] += __low2float(acc) + __high2float(acc);
    }
}

// ---------------- launch (stream-forked, fully joined) ----------------
extern "C" void kernel_launch(void* const* d_in, const int* in_sizes, int n_in,
                              void* d_out, int out_size)
{
    const float* x   = (const float*)d_in[0];
    const float* Wb  = (const float*)d_in[1];
    const float* bb  = (const float*)d_in[2];
    const float* Wr  = (const float*)d_in[3];
    const float* Aw  = (const float*)d_in[4];
    const float* Bw  = (const float*)d_in[5];
    float* out = (float*)d_out;

    void *pXh, *pWh, *pAh, *pBh, *pInterp;
    cudaGetSymbolAddress(&pXh, g_Xh);
    cudaGetSymbolAddress(&pWh, g_Wh);
    cudaGetSymbolAddress(&pAh, g_Ah);
    cudaGetSymbolAddress(&pBh, g_Bh);
    cudaGetSymbolAddress(&pInterp, g_interp);

    cudaFuncSetAttribute(gemm_mma,
                         cudaFuncAttributeMaxDynamicSharedMemorySize, SMEM_BIG);
    cudaFuncSetAttribute(gemm_small,
                         cudaFuncAttributeMaxDynamicSharedMemorySize, SMEM_SMALL);

    static cudaStream_t s1 = [] {
        cudaStream_t s; cudaStreamCreateWithFlags(&s, cudaStreamNonBlocking); return s;
    }();
    static cudaStream_t s2 = [] {
        cudaStream_t s; cudaStreamCreateWithFlags(&s, cudaStreamNonBlocking); return s;
    }();
    static cudaEvent_t evRoot = [] {
        cudaEvent_t e; cudaEventCreateWithFlags(&e, cudaEventDisableTiming); return e;
    }();
    static cudaEvent_t evW = [] {
        cudaEvent_t e; cudaEventCreateWithFlags(&e, cudaEventDisableTiming); return e;
    }();
    static cudaEvent_t evB = [] {
        cudaEvent_t e; cudaEventCreateWithFlags(&e, cudaEventDisableTiming); return e;
    }();
    static cudaEvent_t evX = [] {
        cudaEvent_t e; cudaEventCreateWithFlags(&e, cudaEventDisableTiming); return e;
    }();
    static cudaEvent_t evG = [] {
        cudaEvent_t e; cudaEventCreateWithFlags(&e, cudaEventDisableTiming); return e;
    }();

    // fork side streams off the main (capture) stream
    cudaEventRecord(evRoot, 0);
    cudaStreamWaitEvent(s1, evRoot, 0);
    cudaStreamWaitEvent(s2, evRoot, 0);

    // s1: W convert (gates GEMM), then B convert (gates loraB); both joined below
    convert1_kernel<<<(OUTF * INF / 8 + 255) / 256, 256, 0, s1>>>(
        Wb, (__half*)pWh, OUTF * INF / 8);
    cudaEventRecord(evW, s1);
    convert1_kernel<<<(NEXP * OUTF * RANK / 8 + 255) / 256, 256, 0, s1>>>(
        Bw, (__half*)pBh, NEXP * OUTF * RANK / 8);
    cudaEventRecord(evB, s1);

    // s2: A convert (tiny) then router (fp32 x only)
    convert1_kernel<<<(NEXP * RANK * INF / 8 + 255) / 256, 256, 0, s2>>>(
        Aw, (__half*)pAh, NEXP * RANK * INF / 8);
    router_kernel<<<NTOK, 256, 0, s2>>>(x, Wr);

    // main: x convert
    convert1_kernel<<<(NTOK * INF / 8 + 255) / 256, 256>>>(
        x, (__half*)pXh, NTOK * INF / 8);
    cudaEventRecord(evX, 0);

    // s2: loraA GEMM (needs Xh + Ah) + gather (needs router too)
    cudaStreamWaitEvent(s2, evX, 0);
    gemm_small<<<dim3(1, NTOK / SBM, SPLITK), 256, SMEM_SMALL, s2>>>(
        (const __half*)pXh, (const __half*)pAh, (float*)pInterp);
    gather_kernel<<<(NTOK * 32 + 255) / 256, 256, 0, s2>>>();
    cudaEventRecord(evG, s2);

    // main: base GEMM (needs Wh), then loraB (needs gather + Bh + out)
    cudaStreamWaitEvent(0, evW, 0);
    gemm_mma<<<dim3(OUTF / BN, NTOK / BM), 256, SMEM_BIG>>>(
        (const __half*)pXh, (const __half*)pWh, bb, out);
    cudaStreamWaitEvent(0, evG, 0);
    cudaStreamWaitEvent(0, evB, 0);
    loraB_kernel<<<dim3(OUTF / 128, NTOK / 128), 128>>>(
        (const __half*)pBh, out);
}